// round 6
// baseline (speedup 1.0000x reference)
#include <cuda_runtime.h>
#include <math.h>
#include <stdint.h>

#define BB 2
#define NN 2048
#define MM 2048
#define CC 512
#define KC 16        // K
#define KK1 8        // K1
#define KEY 1024
#define H1D 64
#define H2D 128

// ---------------- device scratch (no allocs allowed) ----------------
__device__ float g_dist[BB * NN * MM];     // 33.5 MB
__device__ float g_scores[BB * NN * MM];   // 33.5 MB
__device__ float g_xx[BB * NN];
__device__ float g_yy[BB * MM];
__device__ float g_corr[BB * 3 * NN];      // src_corr (B,3,N)
__device__ float g_rowmax[BB * NN];        // max of rmm row = 1/sumexp
__device__ float g_slogit[BB * NN];
__device__ float g_weight[BB * NN];
__device__ int   g_topi[BB * KEY];
__device__ float g_R[BB * 9];
__device__ float g_t[BB * 3];

// ---------------- output layout offsets (fp32, tuple order) ----------------
#define OFF_R     0
#define OFF_T     18
#define OFF_SKP   24
#define OFF_TKP   (24 + BB*3*KEY)            // 6168
#define OFF_SKNN  (OFF_TKP + BB*3*KEY)       // 12312
#define OFF_TKNN  (OFF_SKNN + BB*3*KEY*KC)   // 110616
#define OFF_LOSS  (OFF_TKNN + BB*3*KEY*KC)   // 208920

// ================= K1: column squared norms =================
__global__ void k_norms(const float* __restrict__ se, const float* __restrict__ te) {
    int col = blockIdx.x * blockDim.x + threadIdx.x;
    if (col < BB * NN) {
        int b = col / NN, n = col % NN;
        const float* p = se + (size_t)b * CC * NN + n;
        float s = 0.f;
        for (int c = 0; c < CC; c++) { float v = p[(size_t)c * NN]; s += v * v; }
        g_xx[col] = s;
    } else {
        int c2 = col - BB * NN;
        if (c2 < BB * MM) {
            int b = c2 / MM, m = c2 % MM;
            const float* p = te + (size_t)b * CC * MM + m;
            float s = 0.f;
            for (int c = 0; c < CC; c++) { float v = p[(size_t)c * MM]; s += v * v; }
            g_yy[c2] = s;
        }
    }
}

// ================= K2: dist = xx - 2 A^T B + yy (fp32 SGEMM) =================
#define GBM 128
#define GBN 128
#define GBK 16
__global__ __launch_bounds__(256) void k_gemm(const float* __restrict__ A,
                                              const float* __restrict__ Bm) {
    __shared__ float As[GBK][GBM];
    __shared__ float Bs[GBK][GBN];
    int b = blockIdx.z;
    int n0 = blockIdx.y * GBM, m0 = blockIdx.x * GBN;
    const float* Ab = A + (size_t)b * CC * NN;
    const float* Bb = Bm + (size_t)b * CC * MM;
    int tid = threadIdx.x;
    int tx = tid & 15, ty = tid >> 4;
    float acc[8][8] = {};
    for (int c0 = 0; c0 < CC; c0 += GBK) {
        #pragma unroll
        for (int i = 0; i < 8; i++) {
            int e = tid + i * 256;
            int kr = e >> 7, nc = e & 127;
            As[kr][nc] = Ab[(size_t)(c0 + kr) * NN + n0 + nc];
            Bs[kr][nc] = Bb[(size_t)(c0 + kr) * MM + m0 + nc];
        }
        __syncthreads();
        #pragma unroll
        for (int kk = 0; kk < GBK; kk++) {
            float a[8], bv[8];
            float4 a0 = *(const float4*)&As[kk][ty * 8];
            float4 a1 = *(const float4*)&As[kk][ty * 8 + 4];
            float4 b0 = *(const float4*)&Bs[kk][tx * 8];
            float4 b1 = *(const float4*)&Bs[kk][tx * 8 + 4];
            a[0]=a0.x;a[1]=a0.y;a[2]=a0.z;a[3]=a0.w;a[4]=a1.x;a[5]=a1.y;a[6]=a1.z;a[7]=a1.w;
            bv[0]=b0.x;bv[1]=b0.y;bv[2]=b0.z;bv[3]=b0.w;bv[4]=b1.x;bv[5]=b1.y;bv[6]=b1.z;bv[7]=b1.w;
            #pragma unroll
            for (int i = 0; i < 8; i++)
                #pragma unroll
                for (int j = 0; j < 8; j++) acc[i][j] += a[i] * bv[j];
        }
        __syncthreads();
    }
    float* D = g_dist + (size_t)b * NN * MM;
    #pragma unroll
    for (int i = 0; i < 8; i++) {
        int n = n0 + ty * 8 + i;
        float xn = g_xx[b * NN + n];
        #pragma unroll
        for (int j = 0; j < 8; j++) {
            int m = m0 + tx * 8 + j;
            D[(size_t)n * MM + m] = xn - 2.f * acc[i][j] + g_yy[b * MM + m];
        }
    }
}

// ================= K3: scores = softmax(-dist) per row =================
__global__ __launch_bounds__(256) void k_scores() {
    int b = blockIdx.y, n = blockIdx.x, tid = threadIdx.x;
    const float* drow = g_dist + ((size_t)b * NN + n) * MM;
    float* srow = g_scores + ((size_t)b * NN + n) * MM;
    __shared__ float red[256];
    float mn = 1e30f;
    for (int m = tid; m < MM; m += 256) mn = fminf(mn, drow[m]);
    red[tid] = mn; __syncthreads();
    for (int s = 128; s > 0; s >>= 1) { if (tid < s) red[tid] = fminf(red[tid], red[tid + s]); __syncthreads(); }
    mn = red[0]; __syncthreads();
    float sum = 0.f;
    for (int m = tid; m < MM; m += 256) { float e = expf(mn - drow[m]); srow[m] = e; sum += e; }
    red[tid] = sum; __syncthreads();
    for (int s = 128; s > 0; s >>= 1) { if (tid < s) red[tid] += red[tid + s]; __syncthreads(); }
    float inv = 1.f / red[0];
    for (int m = tid; m < MM; m += 256) srow[m] *= inv;
}

// ================= K4: per-row T/S/refined/rmm pipeline =================
__global__ __launch_bounds__(256) void k_rowpipe(const float* __restrict__ tgt,
                                                 const int* __restrict__ idx1,
                                                 const int* __restrict__ idx2) {
    int b = blockIdx.y, n = blockIdx.x, tid = threadIdx.x;
    __shared__ float Tsh[MM];
    __shared__ float Rf[MM];
    __shared__ float red[256];
    __shared__ float red4[4][256];
    const int* i1 = idx1 + ((size_t)b * NN + n) * KK1;
    int r[7];
    #pragma unroll
    for (int j = 0; j < 7; j++) r[j] = i1[j + 1];
    const float* sb = g_scores + (size_t)b * NN * MM;
    for (int m = tid; m < MM; m += 256) {
        float s = 0.f;
        #pragma unroll
        for (int j = 0; j < 7; j++) s += sb[(size_t)r[j] * MM + m];
        Tsh[m] = s;
    }
    __syncthreads();
    const float* drow = g_dist + ((size_t)b * NN + n) * MM;
    const int* ix2 = idx2 + (size_t)b * MM * KK1;
    float mn = 1e30f;
    for (int m = tid; m < MM; m += 256) {
        const int* q = ix2 + (size_t)m * KK1;
        float S = 0.f;
        #pragma unroll
        for (int j = 1; j < KK1; j++) S += Tsh[q[j]];
        float rf = expf(1.0f - S * (1.0f / 7.0f)) * drow[m];
        Rf[m] = rf;
        mn = fminf(mn, rf);
    }
    red[tid] = mn; __syncthreads();
    for (int s = 128; s > 0; s >>= 1) { if (tid < s) red[tid] = fminf(red[tid], red[tid + s]); __syncthreads(); }
    mn = red[0]; __syncthreads();
    const float* t0 = tgt + (size_t)b * 3 * MM;
    float sum = 0.f, c0 = 0.f, c1 = 0.f, c2 = 0.f;
    for (int m = tid; m < MM; m += 256) {
        float e = expf(mn - Rf[m]);
        sum += e;
        c0 += t0[m] * e;
        c1 += t0[MM + m] * e;
        c2 += t0[2 * MM + m] * e;
    }
    red4[0][tid] = sum; red4[1][tid] = c0; red4[2][tid] = c1; red4[3][tid] = c2;
    __syncthreads();
    for (int s = 128; s > 0; s >>= 1) {
        if (tid < s) {
            red4[0][tid] += red4[0][tid + s];
            red4[1][tid] += red4[1][tid + s];
            red4[2][tid] += red4[2][tid + s];
            red4[3][tid] += red4[3][tid + s];
        }
        __syncthreads();
    }
    if (tid == 0) {
        float inv = 1.f / red4[0][0];
        g_corr[b * 3 * NN + n]           = red4[1][0] * inv;
        g_corr[b * 3 * NN + NN + n]      = red4[2][0] * inv;
        g_corr[b * 3 * NN + 2 * NN + n]  = red4[3][0] * inv;
        g_rowmax[b * NN + n] = inv;   // row max of rmm = exp(0)/sum
    }
}

// ================= K5: discriminator MLP + max over K =================
__global__ __launch_bounds__(128) void k_disc(const float* __restrict__ src,
                                              const float* __restrict__ src_knn,
                                              const int* __restrict__ src_idx,
                                              const float* __restrict__ W1, const float* __restrict__ b1,
                                              const float* __restrict__ W2, const float* __restrict__ b2,
                                              const float* __restrict__ W3, const float* __restrict__ b3) {
    __shared__ float W2s[H2D * H1D];
    __shared__ float W1s[H1D * 6];
    __shared__ float b1s[H1D];
    __shared__ float W3s[H2D];
    __shared__ float b2s[H2D];
    int tid = threadIdx.x;
    for (int i = tid; i < H2D * H1D; i += 128) W2s[i] = W2[i];
    for (int i = tid; i < H1D * 6; i += 128) W1s[i] = W1[i];
    if (tid < H1D) b1s[tid] = b1[tid];
    if (tid < H2D) { W3s[tid] = W3[tid]; b2s[tid] = b2[tid]; }
    __syncthreads();
    int gp = blockIdx.x * 8 + (tid >> 4);   // point index over B*N
    int b = gp / NN, n = gp % NN, kk = tid & 15;
    int id = src_idx[((size_t)b * NN + n) * KC + kk];
    const float* cb = g_corr + (size_t)b * 3 * NN;
    const float* sp = src + (size_t)b * 3 * NN;
    const float* skn = src_knn + (((size_t)b * NN + n) * KC + kk) * 3;
    float f[6];
    f[0] = cb[n] - cb[id];
    f[1] = cb[NN + n] - cb[NN + id];
    f[2] = cb[2 * NN + n] - cb[2 * NN + id];
    f[3] = sp[n] - skn[0];
    f[4] = sp[NN + n] - skn[1];
    f[5] = sp[2 * NN + n] - skn[2];
    float h1[H1D];
    #pragma unroll
    for (int d = 0; d < H1D; d++) {
        float a = b1s[d];
        #pragma unroll
        for (int c = 0; c < 6; c++) a += W1s[d * 6 + c] * f[c];
        h1[d] = fmaxf(a, 0.f);
    }
    float s = b3[0];
    for (int e = 0; e < H2D; e++) {
        float a = b2s[e];
        const float4* wr = (const float4*)&W2s[e * H1D];
        #pragma unroll
        for (int d4 = 0; d4 < H1D / 4; d4++) {
            float4 w = wr[d4];
            a += w.x * h1[d4 * 4] + w.y * h1[d4 * 4 + 1] + w.z * h1[d4 * 4 + 2] + w.w * h1[d4 * 4 + 3];
        }
        s += W3s[e] * fmaxf(a, 0.f);
    }
    #pragma unroll
    for (int o = 8; o > 0; o >>= 1) s = fmaxf(s, __shfl_xor_sync(0xffffffffu, s, o));
    if (kk == 0) g_slogit[b * NN + n] = s;
}

// ================= K6: softmax over N -> weight =================
__global__ __launch_bounds__(256) void k_wsoftmax() {
    int b = blockIdx.x, tid = threadIdx.x;
    __shared__ float red[256];
    float mx = -1e30f;
    for (int n = tid; n < NN; n += 256) mx = fmaxf(mx, g_slogit[b * NN + n]);
    red[tid] = mx; __syncthreads();
    for (int s = 128; s > 0; s >>= 1) { if (tid < s) red[tid] = fmaxf(red[tid], red[tid + s]); __syncthreads(); }
    mx = red[0]; __syncthreads();
    float sum = 0.f;
    for (int n = tid; n < NN; n += 256) sum += expf(g_slogit[b * NN + n] - mx);
    red[tid] = sum; __syncthreads();
    for (int s = 128; s > 0; s >>= 1) { if (tid < s) red[tid] += red[tid + s]; __syncthreads(); }
    float inv = 1.f / red[0];
    for (int n = tid; n < NN; n += 256) g_weight[b * NN + n] = expf(g_slogit[b * NN + n] - mx) * inv;
}

// ================= K7: rigid reduction + 3x3 SVD (Kabsch) =================
__device__ double det3d(const double M[3][3]) {
    return M[0][0]*(M[1][1]*M[2][2]-M[1][2]*M[2][1])
         - M[0][1]*(M[1][0]*M[2][2]-M[1][2]*M[2][0])
         + M[0][2]*(M[1][0]*M[2][1]-M[1][1]*M[2][0]);
}

__device__ void jacobi3(double a[3][3], double V[3][3], double w[3]) {
    for (int i = 0; i < 3; i++) for (int j = 0; j < 3; j++) V[i][j] = (i == j) ? 1.0 : 0.0;
    for (int sweep = 0; sweep < 30; sweep++) {
        const int ps[3] = {0, 0, 1}, qs[3] = {1, 2, 2};
        for (int r = 0; r < 3; r++) {
            int p = ps[r], q = qs[r];
            double apq = a[p][q];
            if (fabs(apq) < 1e-300) continue;
            double theta = (a[q][q] - a[p][p]) / (2.0 * apq);
            double t = ((theta >= 0.0) ? 1.0 : -1.0) / (fabs(theta) + sqrt(theta * theta + 1.0));
            double c = 1.0 / sqrt(t * t + 1.0);
            double s = t * c;
            for (int k = 0; k < 3; k++) {
                double akp = a[k][p], akq = a[k][q];
                a[k][p] = c * akp - s * akq;
                a[k][q] = s * akp + c * akq;
            }
            for (int k = 0; k < 3; k++) {
                double apk = a[p][k], aqk = a[q][k];
                a[p][k] = c * apk - s * aqk;
                a[q][k] = s * apk + c * aqk;
            }
            for (int k = 0; k < 3; k++) {
                double vkp = V[k][p], vkq = V[k][q];
                V[k][p] = c * vkp - s * vkq;
                V[k][q] = s * vkp + c * vkq;
            }
        }
    }
    for (int i = 0; i < 3; i++) w[i] = a[i][i];
}

__global__ __launch_bounds__(256) void k_rigid(const float* __restrict__ src, float* __restrict__ out) {
    int b = blockIdx.x, tid = threadIdx.x;
    __shared__ double red[256];
    __shared__ double res[16];
    const float* sp = src + (size_t)b * 3 * NN;
    const float* cb = g_corr + (size_t)b * 3 * NN;
    float acc[16] = {};
    for (int n = tid; n < NN; n += 256) {
        float w = g_weight[b * NN + n];
        float s0 = sp[n], s1 = sp[NN + n], s2 = sp[2 * NN + n];
        float c0 = cb[n], c1 = cb[NN + n], c2 = cb[2 * NN + n];
        acc[0] += w;
        acc[1] += w * s0; acc[2] += w * s1; acc[3] += w * s2;
        acc[4] += w * c0; acc[5] += w * c1; acc[6] += w * c2;
        acc[7]  += w * s0 * c0; acc[8]  += w * s0 * c1; acc[9]  += w * s0 * c2;
        acc[10] += w * s1 * c0; acc[11] += w * s1 * c1; acc[12] += w * s1 * c2;
        acc[13] += w * s2 * c0; acc[14] += w * s2 * c1; acc[15] += w * s2 * c2;
    }
    for (int q = 0; q < 16; q++) {
        red[tid] = (double)acc[q]; __syncthreads();
        for (int s = 128; s > 0; s >>= 1) { if (tid < s) red[tid] += red[tid + s]; __syncthreads(); }
        if (tid == 0) res[q] = red[0];
        __syncthreads();
    }
    if (tid == 0) {
        double sw = res[0];
        double cs[3], ct[3], H[3][3];
        for (int i = 0; i < 3; i++) { cs[i] = res[1 + i] / sw; ct[i] = res[4 + i] / sw; }
        for (int i = 0; i < 3; i++)
            for (int j = 0; j < 3; j++)
                H[i][j] = res[7 + i * 3 + j] / sw - cs[i] * ct[j];
        // A = H^T H
        double A[3][3];
        for (int i = 0; i < 3; i++)
            for (int j = 0; j < 3; j++) {
                double s = 0;
                for (int k = 0; k < 3; k++) s += H[k][i] * H[k][j];
                A[i][j] = s;
            }
        double V[3][3], w[3];
        jacobi3(A, V, w);
        // sort eigenpairs descending
        for (int i = 0; i < 2; i++)
            for (int j = i + 1; j < 3; j++)
                if (w[j] > w[i]) {
                    double tw = w[i]; w[i] = w[j]; w[j] = tw;
                    for (int k = 0; k < 3; k++) { double tv = V[k][i]; V[k][i] = V[k][j]; V[k][j] = tv; }
                }
        double sig[3], U[3][3];
        for (int j = 0; j < 3; j++) sig[j] = sqrt(fmax(w[j], 0.0));
        for (int j = 0; j < 3; j++) {
            double hv[3];
            for (int i = 0; i < 3; i++) {
                double s = 0;
                for (int k = 0; k < 3; k++) s += H[i][k] * V[k][j];
                hv[i] = s;
            }
            if (sig[j] > 1e-12 * fmax(sig[0], 1e-300)) {
                for (int i = 0; i < 3; i++) U[i][j] = hv[i] / sig[j];
            } else {
                // fallback: cross product of first two U columns
                U[0][j] = U[1][0] * U[2][1] - U[2][0] * U[1][1];
                U[1][j] = U[2][0] * U[0][1] - U[0][0] * U[2][1];
                U[2][j] = U[0][0] * U[1][1] - U[1][0] * U[0][1];
            }
        }
        double d = det3d(U) * det3d(V);
        double R[3][3];
        for (int i = 0; i < 3; i++)
            for (int k = 0; k < 3; k++)
                R[i][k] = V[i][0] * U[k][0] + V[i][1] * U[k][1] + d * V[i][2] * U[k][2];
        double tvec[3];
        for (int i = 0; i < 3; i++)
            tvec[i] = ct[i] - (R[i][0] * cs[0] + R[i][1] * cs[1] + R[i][2] * cs[2]);
        for (int i = 0; i < 3; i++) {
            for (int j = 0; j < 3; j++) {
                float rv = (float)R[i][j];
                g_R[b * 9 + i * 3 + j] = rv;
                out[OFF_R + b * 9 + i * 3 + j] = rv;
            }
            float tv = (float)tvec[i];
            g_t[b * 3 + i] = tv;
            out[OFF_T + b * 3 + i] = tv;
        }
    }
}

// ================= K8: stable top-k (rank by count) =================
__global__ __launch_bounds__(1024) void k_topk() {
    int b = blockIdx.x, tid = threadIdx.x;
    __shared__ float wsh[NN];
    for (int n = tid; n < NN; n += 1024) wsh[n] = g_weight[b * NN + n];
    __syncthreads();
    for (int n = tid; n < NN; n += 1024) {
        float v = wsh[n];
        int rank = 0;
        for (int q = 0; q < NN; q++) {
            float u = wsh[q];
            rank += (u > v) || (u == v && q < n);
        }
        if (rank < KEY) g_topi[b * KEY + rank] = n;
    }
}

// ================= K9: gather keypoints + knn outputs =================
__global__ __launch_bounds__(256) void k_outputs(const float* __restrict__ src,
                                                 const int* __restrict__ src_idx,
                                                 float* __restrict__ out) {
    int g = blockIdx.x * blockDim.x + threadIdx.x;
    if (g >= BB * KEY * KC) return;
    int kk = g % KC;
    int j = (g / KC) % KEY;
    int b = g / (KC * KEY);
    int tn = g_topi[b * KEY + j];
    const float* sp = src + (size_t)b * 3 * NN;
    const float* cb = g_corr + (size_t)b * 3 * NN;
    int id = src_idx[((size_t)b * NN + tn) * KC + kk];
    const float* R = g_R + b * 9;
    const float* tt = g_t + b * 3;
    float s0 = sp[tn], s1 = sp[NN + tn], s2 = sp[2 * NN + tn];
    float q0 = sp[id], q1 = sp[NN + id], q2 = sp[2 * NN + id];
    float st[3], sq[3];
    #pragma unroll
    for (int c = 0; c < 3; c++) {
        st[c] = R[c * 3] * s0 + R[c * 3 + 1] * s1 + R[c * 3 + 2] * s2 + tt[c];
        sq[c] = R[c * 3] * q0 + R[c * 3 + 1] * q1 + R[c * 3 + 2] * q2 + tt[c];
    }
    float* skk = out + OFF_SKNN;
    float* tkk = out + OFF_TKNN;
    #pragma unroll
    for (int c = 0; c < 3; c++) {
        size_t o = (((size_t)b * 3 + c) * KEY + j) * KC + kk;
        skk[o] = st[c] - sq[c];
        tkk[o] = cb[c * NN + tn] - cb[c * NN + id];
    }
    if (kk == 0) {
        float* skp = out + OFF_SKP;
        float* tkp = out + OFF_TKP;
        #pragma unroll
        for (int c = 0; c < 3; c++) {
            skp[((size_t)b * 3 + c) * KEY + j] = sp[c * NN + tn];
            tkp[((size_t)b * 3 + c) * KEY + j] = cb[c * NN + tn];
        }
    }
}

// ================= K10: loss =================
__global__ __launch_bounds__(256) void k_loss(float* __restrict__ out) {
    __shared__ double red[256];
    int tid = threadIdx.x;
    double s = 0.0;
    for (int p = tid; p < BB * KEY; p += 256) {
        int b = p / KEY;
        int tn = g_topi[p];
        double pm = (double)g_rowmax[b * NN + tn];
        s += -log(pm + 1e-15);
    }
    red[tid] = s; __syncthreads();
    for (int st = 128; st > 0; st >>= 1) { if (tid < st) red[tid] += red[tid + st]; __syncthreads(); }
    if (tid == 0) out[OFF_LOSS] = (float)(red[0] / (double)(BB * KEY));
}

// ================= launch =================
extern "C" void kernel_launch(void* const* d_in, const int* in_sizes, int n_in,
                              void* d_out, int out_size) {
    const float* src      = (const float*)d_in[0];
    const float* tgt      = (const float*)d_in[1];
    const float* se       = (const float*)d_in[2];
    const float* te       = (const float*)d_in[3];
    const float* src_knn  = (const float*)d_in[4];
    // d_in[5] tgt_knn unused
    const float* W1 = (const float*)d_in[6];
    const float* b1 = (const float*)d_in[7];
    const float* W2 = (const float*)d_in[8];
    const float* b2 = (const float*)d_in[9];
    const float* W3 = (const float*)d_in[10];
    const float* b3 = (const float*)d_in[11];
    const int* src_idx  = (const int*)d_in[12];
    const int* src_idx1 = (const int*)d_in[13];
    const int* idx2     = (const int*)d_in[14];
    float* out = (float*)d_out;

    k_norms<<<(BB * NN + BB * MM) / 256, 256>>>(se, te);
    dim3 gg(MM / GBN, NN / GBM, BB);
    k_gemm<<<gg, 256>>>(se, te);
    dim3 gr(NN, BB);
    k_scores<<<gr, 256>>>();
    k_rowpipe<<<gr, 256>>>(tgt, src_idx1, idx2);
    k_disc<<<BB * NN / 8, 128>>>(src, src_knn, src_idx, W1, b1, W2, b2, W3, b3);
    k_wsoftmax<<<BB, 256>>>();
    k_rigid<<<BB, 256>>>(src, out);
    k_topk<<<BB, 1024>>>();
    k_outputs<<<(BB * KEY * KC + 255) / 256, 256>>>(src, src_idx, out);
    k_loss<<<1, 256>>>(out);
}

// round 10
// speedup vs baseline: 1.6731x; 1.6731x over previous
#include <cuda_runtime.h>
#include <cuda_bf16.h>
#include <math.h>
#include <stdint.h>

#define BB 2
#define NN 2048
#define MM 2048
#define CC 512
#define KC 16        // K
#define KK1 8        // K1
#define KEY 1024
#define H1D 64
#define H2D 128

// ---------------- device scratch (no allocs allowed) ----------------
__device__ float g_dist[BB * NN * MM];     // 33.5 MB
__device__ float g_scores[BB * NN * MM];   // 33.5 MB (unnormalized e = exp(-dist))
__device__ float g_xx[BB * NN];
__device__ float g_yy[BB * MM];
__device__ float g_rowpart[BB * NN * 32];  // per (row, m-block*2 + warp_n) partial sums of e
__device__ float g_rowinv[BB * NN];        // 1 / row sum of e
__device__ float g_corr[BB * 3 * NN];      // src_corr (B,3,N)
__device__ float g_rowmax[BB * NN];        // max of rmm row
__device__ float g_slogit[BB * NN];
__device__ float g_weight[BB * NN];
__device__ int   g_topi[BB * KEY];
__device__ float g_R[BB * 9];
__device__ float g_t[BB * 3];
// bf16 3-way split operands, K-major [b][n][c]
__device__ __nv_bfloat16 g_A1[BB * NN * CC];
__device__ __nv_bfloat16 g_A2[BB * NN * CC];
__device__ __nv_bfloat16 g_A3[BB * NN * CC];
__device__ __nv_bfloat16 g_B1[BB * MM * CC];
__device__ __nv_bfloat16 g_B2[BB * MM * CC];
__device__ __nv_bfloat16 g_B3[BB * MM * CC];

// ---------------- output layout offsets (fp32, tuple order) ----------------
#define OFF_R     0
#define OFF_T     18
#define OFF_SKP   24
#define OFF_TKP   (24 + BB*3*KEY)
#define OFF_SKNN  (OFF_TKP + BB*3*KEY)
#define OFF_TKNN  (OFF_SKNN + BB*3*KEY*KC)
#define OFF_LOSS  (OFF_TKNN + BB*3*KEY*KC)

// ---------------- warp mma helpers (sm_80-era PTX, valid on compute_103) ----
__device__ __forceinline__ uint32_t smem_u32(const void* p) {
    uint32_t a;
    asm("{ .reg .u64 t; cvta.to.shared.u64 t, %1; cvt.u32.u64 %0, t; }" : "=r"(a) : "l"(p));
    return a;
}
__device__ __forceinline__ void ldsm4(uint32_t* r, uint32_t addr) {
    asm volatile("ldmatrix.sync.aligned.m8n8.x4.shared.b16 {%0,%1,%2,%3}, [%4];"
        : "=r"(r[0]), "=r"(r[1]), "=r"(r[2]), "=r"(r[3]) : "r"(addr));
}
__device__ __forceinline__ void ldsm2(uint32_t* r, uint32_t addr) {
    asm volatile("ldmatrix.sync.aligned.m8n8.x2.shared.b16 {%0,%1}, [%2];"
        : "=r"(r[0]), "=r"(r[1]) : "r"(addr));
}
__device__ __forceinline__ void mma16816(float* d, const uint32_t* a, const uint32_t* b) {
    asm volatile(
        "mma.sync.aligned.m16n8k16.row.col.f32.bf16.bf16.f32 "
        "{%0,%1,%2,%3}, {%4,%5,%6,%7}, {%8,%9}, {%0,%1,%2,%3};"
        : "+f"(d[0]), "+f"(d[1]), "+f"(d[2]), "+f"(d[3])
        : "r"(a[0]), "r"(a[1]), "r"(a[2]), "r"(a[3]), "r"(b[0]), "r"(b[1]));
}

// ================= K0: transpose + 3-way bf16 split prep =================
__global__ __launch_bounds__(256) void k_prep(const float* __restrict__ se,
                                              const float* __restrict__ te) {
    __shared__ float t[32][33];
    int zb = blockIdx.z;
    const float* src = (zb < BB) ? se + (size_t)zb * CC * NN : te + (size_t)(zb - BB) * CC * NN;
    __nv_bfloat16* p1 = (zb < BB) ? g_A1 + (size_t)zb * NN * CC : g_B1 + (size_t)(zb - BB) * NN * CC;
    __nv_bfloat16* p2 = (zb < BB) ? g_A2 + (size_t)zb * NN * CC : g_B2 + (size_t)(zb - BB) * NN * CC;
    __nv_bfloat16* p3 = (zb < BB) ? g_A3 + (size_t)zb * NN * CC : g_B3 + (size_t)(zb - BB) * NN * CC;
    int c0 = blockIdx.x * 32, n0 = blockIdx.y * 32;
    int tx = threadIdx.x & 31, ty = threadIdx.x >> 5;
    #pragma unroll
    for (int i = 0; i < 4; i++)
        t[ty + i * 8][tx] = src[(size_t)(c0 + ty + i * 8) * NN + n0 + tx];
    __syncthreads();
    #pragma unroll
    for (int i = 0; i < 4; i++) {
        int n = n0 + ty + i * 8, c = c0 + tx;
        float v = t[tx][ty + i * 8];
        __nv_bfloat16 h1 = __float2bfloat16(v);
        float r1 = v - __bfloat162float(h1);
        __nv_bfloat16 h2 = __float2bfloat16(r1);
        float r2 = r1 - __bfloat162float(h2);
        __nv_bfloat16 h3 = __float2bfloat16(r2);
        p1[(size_t)n * CC + c] = h1;
        p2[(size_t)n * CC + c] = h2;
        p3[(size_t)n * CC + c] = h3;
    }
}

// ================= K1: column squared norms =================
__global__ void k_norms(const float* __restrict__ se, const float* __restrict__ te) {
    int col = blockIdx.x * blockDim.x + threadIdx.x;
    if (col < BB * NN) {
        int b = col / NN, n = col % NN;
        const float* p = se + (size_t)b * CC * NN + n;
        float s = 0.f;
        for (int c = 0; c < CC; c++) { float v = p[(size_t)c * NN]; s += v * v; }
        g_xx[col] = s;
    } else {
        int c2 = col - BB * NN;
        if (c2 < BB * MM) {
            int b = c2 / MM, m = c2 % MM;
            const float* p = te + (size_t)b * CC * MM + m;
            float s = 0.f;
            for (int c = 0; c < CC; c++) { float v = p[(size_t)c * MM]; s += v * v; }
            g_yy[c2] = s;
        }
    }
}

// ================= K2: bf16x6 HMMA GEMM + dist + e epilogue =================
// grid (MM/128, NN/128, BB), block 256 (8 warps: 4 warp_m x 2 warp_n, 32x64 each)
#define RSB 40   // smem row stride in bf16 (80 bytes, ldmatrix conflict-free)
#define TILE_E (128 * RSB)          // elements per smem tile
__global__ __launch_bounds__(256) void k_gemm() {
    extern __shared__ __align__(16) __nv_bfloat16 sm[];
    __shared__ float yys[128];
    __nv_bfloat16* sA1 = sm;
    __nv_bfloat16* sA2 = sm + TILE_E;
    __nv_bfloat16* sA3 = sm + TILE_E * 2;
    __nv_bfloat16* sB1 = sm + TILE_E * 3;
    __nv_bfloat16* sB2 = sm + TILE_E * 4;
    __nv_bfloat16* sB3 = sm + TILE_E * 5;

    int tid = threadIdx.x;
    int wid = tid >> 5, lane = tid & 31;
    int warp_m = wid >> 1, warp_n = wid & 1;
    int b = blockIdx.z;
    int m0 = blockIdx.x * 128, n0 = blockIdx.y * 128;

    const __nv_bfloat16* pA1 = g_A1 + ((size_t)b * NN + n0) * CC;
    const __nv_bfloat16* pA2 = g_A2 + ((size_t)b * NN + n0) * CC;
    const __nv_bfloat16* pA3 = g_A3 + ((size_t)b * NN + n0) * CC;
    const __nv_bfloat16* pB1 = g_B1 + ((size_t)b * MM + m0) * CC;
    const __nv_bfloat16* pB2 = g_B2 + ((size_t)b * MM + m0) * CC;
    const __nv_bfloat16* pB3 = g_B3 + ((size_t)b * MM + m0) * CC;

    if (tid < 128) yys[tid] = g_yy[b * MM + m0 + tid];

    float acc[2][8][4];
    #pragma unroll
    for (int mi = 0; mi < 2; mi++)
        #pragma unroll
        for (int ni = 0; ni < 8; ni++)
            #pragma unroll
            for (int q = 0; q < 4; q++) acc[mi][ni][q] = 0.f;

    uint32_t a1b = smem_u32(sA1 + warp_m * 32 * RSB);
    uint32_t a2b = smem_u32(sA2 + warp_m * 32 * RSB);
    uint32_t a3b = smem_u32(sA3 + warp_m * 32 * RSB);
    uint32_t b1b = smem_u32(sB1 + warp_n * 64 * RSB);
    uint32_t b2b = smem_u32(sB2 + warp_n * 64 * RSB);
    uint32_t b3b = smem_u32(sB3 + warp_n * 64 * RSB);
    uint32_t aoff = (lane & 15) * (RSB * 2) + (lane >> 4) * 16;
    uint32_t boff = (lane & 7) * (RSB * 2) + ((lane >> 3) & 1) * 16;

    int ldrow = tid >> 2, ldseg = tid & 3;          // 64 rows per pass, 4 segs x 16B
    for (int kc = 0; kc < CC / 32; kc++) {
        #pragma unroll
        for (int i = 0; i < 2; i++) {
            int row = ldrow + i * 64;
            size_t go = (size_t)row * CC + kc * 32 + ldseg * 8;
            int so = row * RSB + ldseg * 8;
            *(uint4*)&sA1[so] = *(const uint4*)(pA1 + go);
            *(uint4*)&sA2[so] = *(const uint4*)(pA2 + go);
            *(uint4*)&sA3[so] = *(const uint4*)(pA3 + go);
            *(uint4*)&sB1[so] = *(const uint4*)(pB1 + go);
            *(uint4*)&sB2[so] = *(const uint4*)(pB2 + go);
            *(uint4*)&sB3[so] = *(const uint4*)(pB3 + go);
        }
        __syncthreads();
        #pragma unroll
        for (int ks = 0; ks < 2; ks++) {
            uint32_t a1[2][4], a2[2][4], a3[2][4], bf[8][2];
            uint32_t kso = ks * 32;  // 16 bf16 = 32 bytes
            #pragma unroll
            for (int mi = 0; mi < 2; mi++) {
                ldsm4(a1[mi], a1b + mi * 16 * (RSB * 2) + kso + aoff);
                ldsm4(a2[mi], a2b + mi * 16 * (RSB * 2) + kso + aoff);
                ldsm4(a3[mi], a3b + mi * 16 * (RSB * 2) + kso + aoff);
            }
            // b1: a1*b1, a2*b1, a3*b1
            #pragma unroll
            for (int ni = 0; ni < 8; ni++)
                ldsm2(bf[ni], b1b + ni * 8 * (RSB * 2) + kso + boff);
            #pragma unroll
            for (int mi = 0; mi < 2; mi++)
                #pragma unroll
                for (int ni = 0; ni < 8; ni++) {
                    mma16816(acc[mi][ni], a1[mi], bf[ni]);
                    mma16816(acc[mi][ni], a2[mi], bf[ni]);
                    mma16816(acc[mi][ni], a3[mi], bf[ni]);
                }
            // b2: a1*b2, a2*b2
            #pragma unroll
            for (int ni = 0; ni < 8; ni++)
                ldsm2(bf[ni], b2b + ni * 8 * (RSB * 2) + kso + boff);
            #pragma unroll
            for (int mi = 0; mi < 2; mi++)
                #pragma unroll
                for (int ni = 0; ni < 8; ni++) {
                    mma16816(acc[mi][ni], a1[mi], bf[ni]);
                    mma16816(acc[mi][ni], a2[mi], bf[ni]);
                }
            // b3: a1*b3
            #pragma unroll
            for (int ni = 0; ni < 8; ni++)
                ldsm2(bf[ni], b3b + ni * 8 * (RSB * 2) + kso + boff);
            #pragma unroll
            for (int mi = 0; mi < 2; mi++)
                #pragma unroll
                for (int ni = 0; ni < 8; ni++) mma16816(acc[mi][ni], a1[mi], bf[ni]);
        }
        __syncthreads();
    }

    // ---- epilogue: dist = xx - 2*dot + yy ; e = exp(-dist) ; row partials ----
    int l4 = lane & 3, l2 = lane >> 2;
    int n_base = n0 + warp_m * 32;
    size_t gb = (size_t)b * NN * MM;
    #pragma unroll
    for (int mi = 0; mi < 2; mi++) {
        #pragma unroll
        for (int half = 0; half < 2; half++) {
            int r = mi * 16 + half * 8 + l2;
            int n = n_base + r;
            float xv = g_xx[b * NN + n];
            float rs = 0.f;
            size_t rowo = gb + (size_t)n * MM + m0 + warp_n * 64;
            #pragma unroll
            for (int ni = 0; ni < 8; ni++) {
                int mc = ni * 8 + l4 * 2;
                float v0 = acc[mi][ni][half * 2 + 0];
                float v1 = acc[mi][ni][half * 2 + 1];
                float d0 = xv - 2.f * v0 + yys[warp_n * 64 + mc];
                float d1 = xv - 2.f * v1 + yys[warp_n * 64 + mc + 1];
                float e0 = expf(-d0), e1 = expf(-d1);
                *(float2*)&g_dist[rowo + mc] = make_float2(d0, d1);
                *(float2*)&g_scores[rowo + mc] = make_float2(e0, e1);
                rs += e0 + e1;
            }
            rs += __shfl_xor_sync(0xffffffffu, rs, 1);
            rs += __shfl_xor_sync(0xffffffffu, rs, 2);
            if (l4 == 0)
                g_rowpart[((size_t)b * NN + n) * 32 + blockIdx.x * 2 + warp_n] = rs;
        }
    }
}

// ================= K3: finalize row inverse sums =================
__global__ void k_invsum() {
    int i = blockIdx.x * 256 + threadIdx.x;
    if (i < BB * NN) {
        const float* p = g_rowpart + (size_t)i * 32;
        float s = 0.f;
        #pragma unroll
        for (int j = 0; j < 32; j++) s += p[j];
        g_rowinv[i] = 1.f / s;
    }
}

// ================= K4: per-row T/S/refined/rmm pipeline (NT=4) =================
#define NT 4
__global__ __launch_bounds__(256) void k_rowpipe(const float* __restrict__ tgt,
                                                 const int* __restrict__ idx1,
                                                 const int* __restrict__ idx2) {
    int b = blockIdx.y, n0 = blockIdx.x * NT, tid = threadIdx.x;
    __shared__ float4 T4[MM];        // 32KB
    __shared__ float wred[20][8];
    int r[NT][7]; float inv[NT][7];
    #pragma unroll
    for (int nt = 0; nt < NT; nt++) {
        const int* i1 = idx1 + ((size_t)b * NN + n0 + nt) * KK1;
        #pragma unroll
        for (int j = 0; j < 7; j++) {
            r[nt][j] = i1[j + 1];
            inv[nt][j] = g_rowinv[b * NN + r[nt][j]];
        }
    }
    const float* sb = g_scores + (size_t)b * NN * MM;
    for (int m = tid; m < MM; m += 256) {
        float4 t = {0.f, 0.f, 0.f, 0.f};
        #pragma unroll
        for (int j = 0; j < 7; j++) {
            t.x += sb[(size_t)r[0][j] * MM + m] * inv[0][j];
            t.y += sb[(size_t)r[1][j] * MM + m] * inv[1][j];
            t.z += sb[(size_t)r[2][j] * MM + m] * inv[2][j];
            t.w += sb[(size_t)r[3][j] * MM + m] * inv[3][j];
        }
        T4[m] = t;
    }
    __syncthreads();
    const int* ix2 = idx2 + (size_t)b * MM * KK1;
    const float* t0 = tgt + (size_t)b * 3 * MM;
    const float* d0 = g_dist + ((size_t)b * NN + n0) * MM;
    float sum[NT] = {}, c0[NT] = {}, c1[NT] = {}, c2[NT] = {};
    float mrf[NT] = {1e30f, 1e30f, 1e30f, 1e30f};
    for (int m = tid; m < MM; m += 256) {
        int4 qa = *(const int4*)(ix2 + (size_t)m * KK1);
        int4 qb = *(const int4*)(ix2 + (size_t)m * KK1 + 4);
        float4 S;
        {
            float4 v1 = T4[qa.y], v2 = T4[qa.z], v3 = T4[qa.w];
            float4 v4 = T4[qb.x], v5 = T4[qb.y], v6 = T4[qb.z], v7 = T4[qb.w];
            S.x = v1.x + v2.x + v3.x + v4.x + v5.x + v6.x + v7.x;
            S.y = v1.y + v2.y + v3.y + v4.y + v5.y + v6.y + v7.y;
            S.z = v1.z + v2.z + v3.z + v4.z + v5.z + v6.z + v7.z;
            S.w = v1.w + v2.w + v3.w + v4.w + v5.w + v6.w + v7.w;
        }
        float ty0 = t0[m], ty1 = t0[MM + m], ty2 = t0[2 * MM + m];
        const float* Sp = &S.x;
        #pragma unroll
        for (int nt = 0; nt < NT; nt++) {
            float d = d0[(size_t)nt * MM + m];
            float rf = expf(1.0f - Sp[nt] * (1.0f / 7.0f)) * d;
            float e = expf(-rf);
            sum[nt] += e;
            c0[nt] += ty0 * e; c1[nt] += ty1 * e; c2[nt] += ty2 * e;
            mrf[nt] = fminf(mrf[nt], rf);
        }
    }
    int lane = tid & 31, w = tid >> 5;
    #pragma unroll
    for (int nt = 0; nt < NT; nt++) {
        float v0 = sum[nt], v1 = c0[nt], v2 = c1[nt], v3 = c2[nt], v4 = mrf[nt];
        #pragma unroll
        for (int sh = 16; sh > 0; sh >>= 1) {
            v0 += __shfl_xor_sync(0xffffffffu, v0, sh);
            v1 += __shfl_xor_sync(0xffffffffu, v1, sh);
            v2 += __shfl_xor_sync(0xffffffffu, v2, sh);
            v3 += __shfl_xor_sync(0xffffffffu, v3, sh);
            v4 = fminf(v4, __shfl_xor_sync(0xffffffffu, v4, sh));
        }
        if (lane == 0) {
            wred[nt * 5 + 0][w] = v0; wred[nt * 5 + 1][w] = v1;
            wred[nt * 5 + 2][w] = v2; wred[nt * 5 + 3][w] = v3;
            wred[nt * 5 + 4][w] = v4;
        }
    }
    __syncthreads();
    if (tid < NT) {
        int nt = tid;
        float s = 0.f, a0 = 0.f, a1 = 0.f, a2 = 0.f, mn = 1e30f;
        #pragma unroll
        for (int j = 0; j < 8; j++) {
            s  += wred[nt * 5 + 0][j];
            a0 += wred[nt * 5 + 1][j];
            a1 += wred[nt * 5 + 2][j];
            a2 += wred[nt * 5 + 3][j];
            mn = fminf(mn, wred[nt * 5 + 4][j]);
        }
        float is = 1.f / s;
        int n = n0 + nt;
        g_corr[b * 3 * NN + n]          = a0 * is;
        g_corr[b * 3 * NN + NN + n]     = a1 * is;
        g_corr[b * 3 * NN + 2 * NN + n] = a2 * is;
        g_rowmax[b * NN + n] = expf(-mn) * is;
    }
}

// ================= K5: discriminator MLP + max over K =================
__global__ __launch_bounds__(128) void k_disc(const float* __restrict__ src,
                                              const float* __restrict__ src_knn,
                                              const int* __restrict__ src_idx,
                                              const float* __restrict__ W1, const float* __restrict__ b1,
                                              const float* __restrict__ W2, const float* __restrict__ b2,
                                              const float* __restrict__ W3, const float* __restrict__ b3) {
    __shared__ float W2s[H2D * H1D];
    __shared__ float W1s[H1D * 6];
    __shared__ float b1s[H1D];
    __shared__ float W3s[H2D];
    __shared__ float b2s[H2D];
    int tid = threadIdx.x;
    for (int i = tid; i < H2D * H1D; i += 128) W2s[i] = W2[i];
    for (int i = tid; i < H1D * 6; i += 128) W1s[i] = W1[i];
    if (tid < H1D) b1s[tid] = b1[tid];
    if (tid < H2D) { W3s[tid] = W3[tid]; b2s[tid] = b2[tid]; }
    __syncthreads();
    int gp = blockIdx.x * 8 + (tid >> 4);
    int b = gp / NN, n = gp % NN, kk = tid & 15;
    int id = src_idx[((size_t)b * NN + n) * KC + kk];
    const float* cb = g_corr + (size_t)b * 3 * NN;
    const float* sp = src + (size_t)b * 3 * NN;
    const float* skn = src_knn + (((size_t)b * NN + n) * KC + kk) * 3;
    float f[6];
    f[0] = cb[n] - cb[id];
    f[1] = cb[NN + n] - cb[NN + id];
    f[2] = cb[2 * NN + n] - cb[2 * NN + id];
    f[3] = sp[n] - skn[0];
    f[4] = sp[NN + n] - skn[1];
    f[5] = sp[2 * NN + n] - skn[2];
    float h1[H1D];
    #pragma unroll
    for (int d = 0; d < H1D; d++) {
        float a = b1s[d];
        #pragma unroll
        for (int c = 0; c < 6; c++) a += W1s[d * 6 + c] * f[c];
        h1[d] = fmaxf(a, 0.f);
    }
    float s = b3[0];
    for (int e = 0; e < H2D; e++) {
        float a = b2s[e];
        const float4* wr = (const float4*)&W2s[e * H1D];
        #pragma unroll
        for (int d4 = 0; d4 < H1D / 4; d4++) {
            float4 w = wr[d4];
            a += w.x * h1[d4 * 4] + w.y * h1[d4 * 4 + 1] + w.z * h1[d4 * 4 + 2] + w.w * h1[d4 * 4 + 3];
        }
        s += W3s[e] * fmaxf(a, 0.f);
    }
    #pragma unroll
    for (int o = 8; o > 0; o >>= 1) s = fmaxf(s, __shfl_xor_sync(0xffffffffu, s, o));
    if (kk == 0) g_slogit[b * NN + n] = s;
}

// ================= K6: softmax over N -> weight =================
__global__ __launch_bounds__(256) void k_wsoftmax() {
    int b = blockIdx.x, tid = threadIdx.x;
    __shared__ float red[256];
    float mx = -1e30f;
    for (int n = tid; n < NN; n += 256) mx = fmaxf(mx, g_slogit[b * NN + n]);
    red[tid] = mx; __syncthreads();
    for (int s = 128; s > 0; s >>= 1) { if (tid < s) red[tid] = fmaxf(red[tid], red[tid + s]); __syncthreads(); }
    mx = red[0]; __syncthreads();
    float sum = 0.f;
    for (int n = tid; n < NN; n += 256) sum += expf(g_slogit[b * NN + n] - mx);
    red[tid] = sum; __syncthreads();
    for (int s = 128; s > 0; s >>= 1) { if (tid < s) red[tid] += red[tid + s]; __syncthreads(); }
    float inv = 1.f / red[0];
    for (int n = tid; n < NN; n += 256) g_weight[b * NN + n] = expf(g_slogit[b * NN + n] - mx) * inv;
}

// ================= K7: rigid reduction + 3x3 SVD (Kabsch) =================
__device__ double det3d(const double M[3][3]) {
    return M[0][0]*(M[1][1]*M[2][2]-M[1][2]*M[2][1])
         - M[0][1]*(M[1][0]*M[2][2]-M[1][2]*M[2][0])
         + M[0][2]*(M[1][0]*M[2][1]-M[1][1]*M[2][0]);
}
__device__ void jacobi3(double a[3][3], double V[3][3], double w[3]) {
    for (int i = 0; i < 3; i++) for (int j = 0; j < 3; j++) V[i][j] = (i == j) ? 1.0 : 0.0;
    for (int sweep = 0; sweep < 15; sweep++) {
        const int ps[3] = {0, 0, 1}, qs[3] = {1, 2, 2};
        for (int rr = 0; rr < 3; rr++) {
            int p = ps[rr], q = qs[rr];
            double apq = a[p][q];
            if (fabs(apq) < 1e-300) continue;
            double theta = (a[q][q] - a[p][p]) / (2.0 * apq);
            double t = ((theta >= 0.0) ? 1.0 : -1.0) / (fabs(theta) + sqrt(theta * theta + 1.0));
            double c = 1.0 / sqrt(t * t + 1.0);
            double s = t * c;
            for (int k = 0; k < 3; k++) {
                double akp = a[k][p], akq = a[k][q];
                a[k][p] = c * akp - s * akq;
                a[k][q] = s * akp + c * akq;
            }
            for (int k = 0; k < 3; k++) {
                double apk = a[p][k], aqk = a[q][k];
                a[p][k] = c * apk - s * aqk;
                a[q][k] = s * apk + c * aqk;
            }
            for (int k = 0; k < 3; k++) {
                double vkp = V[k][p], vkq = V[k][q];
                V[k][p] = c * vkp - s * vkq;
                V[k][q] = s * vkp + c * vkq;
            }
        }
    }
    for (int i = 0; i < 3; i++) w[i] = a[i][i];
}
__global__ __launch_bounds__(256) void k_rigid(const float* __restrict__ src, float* __restrict__ out) {
    int b = blockIdx.x, tid = threadIdx.x;
    __shared__ float wp[16][8];
    __shared__ double res[16];
    const float* sp = src + (size_t)b * 3 * NN;
    const float* cb = g_corr + (size_t)b * 3 * NN;
    float acc[16] = {};
    for (int n = tid; n < NN; n += 256) {
        float w = g_weight[b * NN + n];
        float s0 = sp[n], s1 = sp[NN + n], s2 = sp[2 * NN + n];
        float c0 = cb[n], c1 = cb[NN + n], c2 = cb[2 * NN + n];
        acc[0] += w;
        acc[1] += w * s0; acc[2] += w * s1; acc[3] += w * s2;
        acc[4] += w * c0; acc[5] += w * c1; acc[6] += w * c2;
        acc[7]  += w * s0 * c0; acc[8]  += w * s0 * c1; acc[9]  += w * s0 * c2;
        acc[10] += w * s1 * c0; acc[11] += w * s1 * c1; acc[12] += w * s1 * c2;
        acc[13] += w * s2 * c0; acc[14] += w * s2 * c1; acc[15] += w * s2 * c2;
    }
    int lane = tid & 31, w8 = tid >> 5;
    #pragma unroll
    for (int q = 0; q < 16; q++) {
        float v = acc[q];
        #pragma unroll
        for (int sh = 16; sh > 0; sh >>= 1) v += __shfl_xor_sync(0xffffffffu, v, sh);
        if (lane == 0) wp[q][w8] = v;
    }
    __syncthreads();
    if (tid < 16) {
        double s = 0.0;
        for (int j = 0; j < 8; j++) s += (double)wp[tid][j];
        res[tid] = s;
    }
    __syncthreads();
    if (tid == 0) {
        double sw = res[0];
        double cs[3], ct[3], H[3][3];
        for (int i = 0; i < 3; i++) { cs[i] = res[1 + i] / sw; ct[i] = res[4 + i] / sw; }
        for (int i = 0; i < 3; i++)
            for (int j = 0; j < 3; j++)
                H[i][j] = res[7 + i * 3 + j] / sw - cs[i] * ct[j];
        double A[3][3];
        for (int i = 0; i < 3; i++)
            for (int j = 0; j < 3; j++) {
                double s = 0;
                for (int k = 0; k < 3; k++) s += H[k][i] * H[k][j];
                A[i][j] = s;
            }
        double V[3][3], wv[3];
        jacobi3(A, V, wv);
        for (int i = 0; i < 2; i++)
            for (int j = i + 1; j < 3; j++)
                if (wv[j] > wv[i]) {
                    double tw = wv[i]; wv[i] = wv[j]; wv[j] = tw;
                    for (int k = 0; k < 3; k++) { double tv = V[k][i]; V[k][i] = V[k][j]; V[k][j] = tv; }
                }
        double sig[3], U[3][3];
        for (int j = 0; j < 3; j++) sig[j] = sqrt(fmax(wv[j], 0.0));
        for (int j = 0; j < 3; j++) {
            double hv[3];
            for (int i = 0; i < 3; i++) {
                double s = 0;
                for (int k = 0; k < 3; k++) s += H[i][k] * V[k][j];
                hv[i] = s;
            }
            if (sig[j] > 1e-12 * fmax(sig[0], 1e-300)) {
                for (int i = 0; i < 3; i++) U[i][j] = hv[i] / sig[j];
            } else {
                U[0][j] = U[1][0] * U[2][1] - U[2][0] * U[1][1];
                U[1][j] = U[2][0] * U[0][1] - U[0][0] * U[2][1];
                U[2][j] = U[0][0] * U[1][1] - U[1][0] * U[0][1];
            }
        }
        double d = det3d(U) * det3d(V);
        double R[3][3];
        for (int i = 0; i < 3; i++)
            for (int k = 0; k < 3; k++)
                R[i][k] = V[i][0] * U[k][0] + V[i][1] * U[k][1] + d * V[i][2] * U[k][2];
        double tvec[3];
        for (int i = 0; i < 3; i++)
            tvec[i] = ct[i] - (R[i][0] * cs[0] + R[i][1] * cs[1] + R[i][2] * cs[2]);
        for (int i = 0; i < 3; i++) {
            for (int j = 0; j < 3; j++) {
                float rv = (float)R[i][j];
                g_R[b * 9 + i * 3 + j] = rv;
                out[OFF_R + b * 9 + i * 3 + j] = rv;
            }
            float tv = (float)tvec[i];
            g_t[b * 3 + i] = tv;
            out[OFF_T + b * 3 + i] = tv;
        }
    }
}

// ================= K8: stable top-k (rank by count), parallel =================
__global__ __launch_bounds__(256) void k_topk() {
    int b = blockIdx.x >> 4;
    int base = (blockIdx.x & 15) * 128;
    int tid = threadIdx.x;
    __shared__ float wsh[NN];
    for (int n = tid; n < NN; n += 256) wsh[n] = g_weight[b * NN + n];
    __syncthreads();
    int n = base + (tid >> 1);
    int half = tid & 1;
    float v = wsh[n];
    int rank = 0;
    int q0 = half * (NN / 2), q1 = q0 + NN / 2;
    for (int q = q0; q < q1; q++) {
        float u = wsh[q];
        rank += (u > v) || (u == v && q < n);
    }
    rank += __shfl_xor_sync(0xffffffffu, rank, 1);
    if (half == 0 && rank < KEY) g_topi[b * KEY + rank] = n;
}

// ================= K9: gather keypoints + knn outputs =================
__global__ __launch_bounds__(256) void k_outputs(const float* __restrict__ src,
                                                 const int* __restrict__ src_idx,
                                                 float* __restrict__ out) {
    int g = blockIdx.x * blockDim.x + threadIdx.x;
    if (g >= BB * KEY * KC) return;
    int kk = g % KC;
    int j = (g / KC) % KEY;
    int b = g / (KC * KEY);
    int tn = g_topi[b * KEY + j];
    const float* sp = src + (size_t)b * 3 * NN;
    const float* cb = g_corr + (size_t)b * 3 * NN;
    int id = src_idx[((size_t)b * NN + tn) * KC + kk];
    const float* R = g_R + b * 9;
    const float* tt = g_t + b * 3;
    float s0 = sp[tn], s1 = sp[NN + tn], s2 = sp[2 * NN + tn];
    float q0 = sp[id], q1 = sp[NN + id], q2 = sp[2 * NN + id];
    float st[3], sq[3];
    #pragma unroll
    for (int c = 0; c < 3; c++) {
        st[c] = R[c * 3] * s0 + R[c * 3 + 1] * s1 + R[c * 3 + 2] * s2 + tt[c];
        sq[c] = R[c * 3] * q0 + R[c * 3 + 1] * q1 + R[c * 3 + 2] * q2 + tt[c];
    }
    float* skk = out + OFF_SKNN;
    float* tkk = out + OFF_TKNN;
    #pragma unroll
    for (int c = 0; c < 3; c++) {
        size_t o = (((size_t)b * 3 + c) * KEY + j) * KC + kk;
        skk[o] = st[c] - sq[c];
        tkk[o] = cb[c * NN + tn] - cb[c * NN + id];
    }
    if (kk == 0) {
        float* skp = out + OFF_SKP;
        float* tkp = out + OFF_TKP;
        #pragma unroll
        for (int c = 0; c < 3; c++) {
            skp[((size_t)b * 3 + c) * KEY + j] = sp[c * NN + tn];
            tkp[((size_t)b * 3 + c) * KEY + j] = cb[c * NN + tn];
        }
    }
}

// ================= K10: loss =================
__global__ __launch_bounds__(256) void k_loss(float* __restrict__ out) {
    __shared__ double red[256];
    int tid = threadIdx.x;
    double s = 0.0;
    for (int p = tid; p < BB * KEY; p += 256) {
        int b = p / KEY;
        int tn = g_topi[p];
        double pm = (double)g_rowmax[b * NN + tn];
        s += -log(pm + 1e-15);
    }
    red[tid] = s; __syncthreads();
    for (int st = 128; st > 0; st >>= 1) { if (tid < st) red[tid] += red[tid + st]; __syncthreads(); }
    if (tid == 0) out[OFF_LOSS] = (float)(red[0] / (double)(BB * KEY));
}

// ================= launch =================
extern "C" void kernel_launch(void* const* d_in, const int* in_sizes, int n_in,
                              void* d_out, int out_size) {
    const float* src      = (const float*)d_in[0];
    const float* tgt      = (const float*)d_in[1];
    const float* se       = (const float*)d_in[2];
    const float* te       = (const float*)d_in[3];
    const float* src_knn  = (const float*)d_in[4];
    const float* W1 = (const float*)d_in[6];
    const float* b1 = (const float*)d_in[7];
    const float* W2 = (const float*)d_in[8];
    const float* b2 = (const float*)d_in[9];
    const float* W3 = (const float*)d_in[10];
    const float* b3 = (const float*)d_in[11];
    const int* src_idx  = (const int*)d_in[12];
    const int* src_idx1 = (const int*)d_in[13];
    const int* idx2     = (const int*)d_in[14];
    float* out = (float*)d_out;

    const int smem_gemm = 6 * TILE_E * (int)sizeof(__nv_bfloat16) + 256;  // ~61.7KB
    cudaFuncSetAttribute(k_gemm, cudaFuncAttributeMaxDynamicSharedMemorySize, smem_gemm);

    dim3 gp(CC / 32, NN / 32, 2 * BB);
    k_prep<<<gp, 256>>>(se, te);
    k_norms<<<(BB * NN + BB * MM) / 256, 256>>>(se, te);
    dim3 gg(MM / 128, NN / 128, BB);
    k_gemm<<<gg, 256, smem_gemm>>>();
    k_invsum<<<(BB * NN + 255) / 256, 256>>>();
    dim3 gr(NN / NT, BB);
    k_rowpipe<<<gr, 256>>>(tgt, src_idx1, idx2);
    k_disc<<<BB * NN / 8, 128>>>(src, src_knn, src_idx, W1, b1, W2, b2, W3, b3);
    k_wsoftmax<<<BB, 256>>>();
    k_rigid<<<BB, 256>>>(src, out);
    k_topk<<<BB * 16, 256>>>();
    k_outputs<<<(BB * KEY * KC + 255) / 256, 256>>>(src, src_idx, out);
    k_loss<<<1, 256>>>(out);
}

// round 13
// speedup vs baseline: 1.7588x; 1.0512x over previous
#include <cuda_runtime.h>
#include <cuda_bf16.h>
#include <math.h>
#include <stdint.h>

#define BB 2
#define NN 2048
#define MM 2048
#define CC 512
#define KC 16        // K
#define KK1 8        // K1
#define KEY 1024
#define H1D 64
#define H2D 128

// ---------------- device scratch (no allocs allowed) ----------------
__device__ float g_dist[BB * NN * MM];     // 33.5 MB
__device__ float g_scores[BB * NN * MM];   // 33.5 MB (unnormalized e = exp(-dist))
__device__ float g_xx[BB * NN];
__device__ float g_yy[BB * MM];
__device__ float g_rowpart[BB * NN * 32];  // per (row, m-block*2 + warp_n) partial sums of e
__device__ float g_rowinv[BB * NN];        // 1 / row sum of e
__device__ float g_corr[BB * 3 * NN];      // src_corr (B,3,N)
__device__ float g_rowmax[BB * NN];        // max of rmm row
__device__ float g_slogit[BB * NN];
__device__ float g_weight[BB * NN];
__device__ int   g_topi[BB * KEY];
__device__ float g_R[BB * 9];
__device__ float g_t[BB * 3];
// bf16 3-way split operands, K-major [b][n][c]
__device__ __nv_bfloat16 g_A1[BB * NN * CC];
__device__ __nv_bfloat16 g_A2[BB * NN * CC];
__device__ __nv_bfloat16 g_A3[BB * NN * CC];
__device__ __nv_bfloat16 g_B1[BB * MM * CC];
__device__ __nv_bfloat16 g_B2[BB * MM * CC];
__device__ __nv_bfloat16 g_B3[BB * MM * CC];

// ---------------- output layout offsets (fp32, tuple order) ----------------
#define OFF_R     0
#define OFF_T     18
#define OFF_SKP   24
#define OFF_TKP   (24 + BB*3*KEY)
#define OFF_SKNN  (OFF_TKP + BB*3*KEY)
#define OFF_TKNN  (OFF_SKNN + BB*3*KEY*KC)
#define OFF_LOSS  (OFF_TKNN + BB*3*KEY*KC)

// ---------------- warp mma + cp.async helpers (compute_103-safe) ----------
__device__ __forceinline__ uint32_t smem_u32(const void* p) {
    uint32_t a;
    asm("{ .reg .u64 t; cvta.to.shared.u64 t, %1; cvt.u32.u64 %0, t; }" : "=r"(a) : "l"(p));
    return a;
}
__device__ __forceinline__ void ldsm4(uint32_t* r, uint32_t addr) {
    asm volatile("ldmatrix.sync.aligned.m8n8.x4.shared.b16 {%0,%1,%2,%3}, [%4];"
        : "=r"(r[0]), "=r"(r[1]), "=r"(r[2]), "=r"(r[3]) : "r"(addr));
}
__device__ __forceinline__ void ldsm2(uint32_t* r, uint32_t addr) {
    asm volatile("ldmatrix.sync.aligned.m8n8.x2.shared.b16 {%0,%1}, [%2];"
        : "=r"(r[0]), "=r"(r[1]) : "r"(addr));
}
__device__ __forceinline__ void mma16816(float* d, const uint32_t* a, const uint32_t* b) {
    asm volatile(
        "mma.sync.aligned.m16n8k16.row.col.f32.bf16.bf16.f32 "
        "{%0,%1,%2,%3}, {%4,%5,%6,%7}, {%8,%9}, {%0,%1,%2,%3};"
        : "+f"(d[0]), "+f"(d[1]), "+f"(d[2]), "+f"(d[3])
        : "r"(a[0]), "r"(a[1]), "r"(a[2]), "r"(a[3]), "r"(b[0]), "r"(b[1]));
}
__device__ __forceinline__ void cp16(uint32_t saddr, const void* gaddr) {
    asm volatile("cp.async.cg.shared.global [%0], [%1], 16;" :: "r"(saddr), "l"(gaddr));
}
#define CP_COMMIT() asm volatile("cp.async.commit_group;" ::: "memory")
#define CP_WAIT0()  asm volatile("cp.async.wait_group 0;" ::: "memory")

// ================= K0: transpose + 3-way bf16 split prep =================
__global__ __launch_bounds__(256) void k_prep(const float* __restrict__ se,
                                              const float* __restrict__ te) {
    __shared__ float t[32][33];
    int zb = blockIdx.z;
    const float* src = (zb < BB) ? se + (size_t)zb * CC * NN : te + (size_t)(zb - BB) * CC * NN;
    __nv_bfloat16* p1 = (zb < BB) ? g_A1 + (size_t)zb * NN * CC : g_B1 + (size_t)(zb - BB) * NN * CC;
    __nv_bfloat16* p2 = (zb < BB) ? g_A2 + (size_t)zb * NN * CC : g_B2 + (size_t)(zb - BB) * NN * CC;
    __nv_bfloat16* p3 = (zb < BB) ? g_A3 + (size_t)zb * NN * CC : g_B3 + (size_t)(zb - BB) * NN * CC;
    int c0 = blockIdx.x * 32, n0 = blockIdx.y * 32;
    int tx = threadIdx.x & 31, ty = threadIdx.x >> 5;
    #pragma unroll
    for (int i = 0; i < 4; i++)
        t[ty + i * 8][tx] = src[(size_t)(c0 + ty + i * 8) * NN + n0 + tx];
    __syncthreads();
    #pragma unroll
    for (int i = 0; i < 4; i++) {
        int n = n0 + ty + i * 8, c = c0 + tx;
        float v = t[tx][ty + i * 8];
        __nv_bfloat16 h1 = __float2bfloat16(v);
        float r1 = v - __bfloat162float(h1);
        __nv_bfloat16 h2 = __float2bfloat16(r1);
        float r2 = r1 - __bfloat162float(h2);
        __nv_bfloat16 h3 = __float2bfloat16(r2);
        p1[(size_t)n * CC + c] = h1;
        p2[(size_t)n * CC + c] = h2;
        p3[(size_t)n * CC + c] = h3;
    }
}

// ================= K1: column squared norms =================
__global__ void k_norms(const float* __restrict__ se, const float* __restrict__ te) {
    int col = blockIdx.x * blockDim.x + threadIdx.x;
    if (col < BB * NN) {
        int b = col / NN, n = col % NN;
        const float* p = se + (size_t)b * CC * NN + n;
        float s = 0.f;
        for (int c = 0; c < CC; c++) { float v = p[(size_t)c * NN]; s += v * v; }
        g_xx[col] = s;
    } else {
        int c2 = col - BB * NN;
        if (c2 < BB * MM) {
            int b = c2 / MM, m = c2 % MM;
            const float* p = te + (size_t)b * CC * MM + m;
            float s = 0.f;
            for (int c = 0; c < CC; c++) { float v = p[(size_t)c * MM]; s += v * v; }
            g_yy[c2] = s;
        }
    }
}

// ================= K2: bf16x6 HMMA GEMM, cp.async double-buffered =========
// grid (MM/128, NN/128, BB), block 256 (8 warps: 4 warp_m x 2 warp_n)
#define RSB 40                      // smem row stride in bf16 (80B, 16B-aligned, ldmatrix conflict-free)
#define TILE_E (128 * RSB)          // elements per operand tile
#define STAGE_E (6 * TILE_E)        // 6 operand tiles per stage
__global__ __launch_bounds__(256) void k_gemm() {
    extern __shared__ __align__(16) __nv_bfloat16 sm[];   // 2 stages x 6 tiles
    __shared__ float yys[128];

    int tid = threadIdx.x;
    int wid = tid >> 5, lane = tid & 31;
    int warp_m = wid >> 1, warp_n = wid & 1;
    int b = blockIdx.z;
    int m0 = blockIdx.x * 128, n0 = blockIdx.y * 128;

    const __nv_bfloat16* ptrs[6];
    ptrs[0] = g_A1 + ((size_t)b * NN + n0) * CC;
    ptrs[1] = g_A2 + ((size_t)b * NN + n0) * CC;
    ptrs[2] = g_A3 + ((size_t)b * NN + n0) * CC;
    ptrs[3] = g_B1 + ((size_t)b * MM + m0) * CC;
    ptrs[4] = g_B2 + ((size_t)b * MM + m0) * CC;
    ptrs[5] = g_B3 + ((size_t)b * MM + m0) * CC;

    if (tid < 128) yys[tid] = g_yy[b * MM + m0 + tid];

    float acc[2][8][4];
    #pragma unroll
    for (int mi = 0; mi < 2; mi++)
        #pragma unroll
        for (int ni = 0; ni < 8; ni++)
            #pragma unroll
            for (int q = 0; q < 4; q++) acc[mi][ni][q] = 0.f;

    uint32_t smb = smem_u32(sm);
    int ldrow = tid >> 2, ldseg = tid & 3;   // per tile: 2 passes of 64 rows, 4x16B segs

    // ldmatrix per-warp offsets (within a tile, bytes)
    uint32_t aoff = (lane & 15) * (RSB * 2) + (lane >> 4) * 16 + warp_m * 32 * (RSB * 2);
    uint32_t boff = (lane & 7) * (RSB * 2) + ((lane >> 3) & 1) * 16 + warp_n * 64 * (RSB * 2);

    // ---- prefetch stage 0 ----
    #pragma unroll
    for (int t = 0; t < 6; t++)
        #pragma unroll
        for (int i = 0; i < 2; i++) {
            int row = ldrow + i * 64;
            cp16(smb + (uint32_t)(t * TILE_E + row * RSB + ldseg * 8) * 2,
                 ptrs[t] + (size_t)row * CC + ldseg * 8);
        }
    CP_COMMIT();

    for (int kc = 0; kc < CC / 32; kc++) {
        CP_WAIT0();
        __syncthreads();
        uint32_t stage = (uint32_t)(kc & 1) * STAGE_E * 2;   // byte offset of current stage
        // prefetch next stage
        if (kc + 1 < CC / 32) {
            uint32_t nst = (uint32_t)((kc + 1) & 1) * STAGE_E * 2;
            #pragma unroll
            for (int t = 0; t < 6; t++)
                #pragma unroll
                for (int i = 0; i < 2; i++) {
                    int row = ldrow + i * 64;
                    cp16(smb + nst + (uint32_t)(t * TILE_E + row * RSB + ldseg * 8) * 2,
                         ptrs[t] + (size_t)row * CC + (kc + 1) * 32 + ldseg * 8);
                }
            CP_COMMIT();
        }
        // compute current stage
        uint32_t a1b = smb + stage + aoff;
        uint32_t a2b = smb + stage + (uint32_t)TILE_E * 2 + aoff;
        uint32_t a3b = smb + stage + (uint32_t)TILE_E * 4 + aoff;
        uint32_t b1b = smb + stage + (uint32_t)TILE_E * 6 + boff;
        uint32_t b2b = smb + stage + (uint32_t)TILE_E * 8 + boff;
        uint32_t b3b = smb + stage + (uint32_t)TILE_E * 10 + boff;
        #pragma unroll
        for (int ks = 0; ks < 2; ks++) {
            uint32_t a1[2][4], a2[2][4], a3[2][4], bf[8][2];
            uint32_t kso = ks * 32;
            #pragma unroll
            for (int mi = 0; mi < 2; mi++) {
                ldsm4(a1[mi], a1b + mi * 16 * (RSB * 2) + kso);
                ldsm4(a2[mi], a2b + mi * 16 * (RSB * 2) + kso);
                ldsm4(a3[mi], a3b + mi * 16 * (RSB * 2) + kso);
            }
            #pragma unroll
            for (int ni = 0; ni < 8; ni++)
                ldsm2(bf[ni], b1b + ni * 8 * (RSB * 2) + kso);
            #pragma unroll
            for (int mi = 0; mi < 2; mi++)
                #pragma unroll
                for (int ni = 0; ni < 8; ni++) {
                    mma16816(acc[mi][ni], a1[mi], bf[ni]);
                    mma16816(acc[mi][ni], a2[mi], bf[ni]);
                    mma16816(acc[mi][ni], a3[mi], bf[ni]);
                }
            #pragma unroll
            for (int ni = 0; ni < 8; ni++)
                ldsm2(bf[ni], b2b + ni * 8 * (RSB * 2) + kso);
            #pragma unroll
            for (int mi = 0; mi < 2; mi++)
                #pragma unroll
                for (int ni = 0; ni < 8; ni++) {
                    mma16816(acc[mi][ni], a1[mi], bf[ni]);
                    mma16816(acc[mi][ni], a2[mi], bf[ni]);
                }
            #pragma unroll
            for (int ni = 0; ni < 8; ni++)
                ldsm2(bf[ni], b3b + ni * 8 * (RSB * 2) + kso);
            #pragma unroll
            for (int mi = 0; mi < 2; mi++)
                #pragma unroll
                for (int ni = 0; ni < 8; ni++) mma16816(acc[mi][ni], a1[mi], bf[ni]);
        }
    }
    __syncthreads();

    // ---- epilogue: dist = xx - 2*dot + yy ; e = exp(-dist) ; row partials ----
    int l4 = lane & 3, l2 = lane >> 2;
    int n_base = n0 + warp_m * 32;
    size_t gb = (size_t)b * NN * MM;
    #pragma unroll
    for (int mi = 0; mi < 2; mi++) {
        #pragma unroll
        for (int half = 0; half < 2; half++) {
            int r = mi * 16 + half * 8 + l2;
            int n = n_base + r;
            float xv = g_xx[b * NN + n];
            float rs = 0.f;
            size_t rowo = gb + (size_t)n * MM + m0 + warp_n * 64;
            #pragma unroll
            for (int ni = 0; ni < 8; ni++) {
                int mc = ni * 8 + l4 * 2;
                float v0 = acc[mi][ni][half * 2 + 0];
                float v1 = acc[mi][ni][half * 2 + 1];
                float d0 = xv - 2.f * v0 + yys[warp_n * 64 + mc];
                float d1 = xv - 2.f * v1 + yys[warp_n * 64 + mc + 1];
                float e0 = expf(-d0), e1 = expf(-d1);
                *(float2*)&g_dist[rowo + mc] = make_float2(d0, d1);
                *(float2*)&g_scores[rowo + mc] = make_float2(e0, e1);
                rs += e0 + e1;
            }
            rs += __shfl_xor_sync(0xffffffffu, rs, 1);
            rs += __shfl_xor_sync(0xffffffffu, rs, 2);
            if (l4 == 0)
                g_rowpart[((size_t)b * NN + n) * 32 + blockIdx.x * 2 + warp_n] = rs;
        }
    }
}

// ================= K3: finalize row inverse sums (warp per row) =========
__global__ __launch_bounds__(256) void k_invsum() {
    int w = (blockIdx.x * 256 + threadIdx.x) >> 5;   // row index
    int lane = threadIdx.x & 31;
    if (w < BB * NN) {
        float s = g_rowpart[(size_t)w * 32 + lane];
        #pragma unroll
        for (int sh = 16; sh > 0; sh >>= 1) s += __shfl_xor_sync(0xffffffffu, s, sh);
        if (lane == 0) g_rowinv[w] = 1.f / s;
    }
}

// ================= K4: per-row T/S/refined/rmm pipeline (NT=4) =================
#define NT 4
__global__ __launch_bounds__(256) void k_rowpipe(const float* __restrict__ tgt,
                                                 const int* __restrict__ idx1,
                                                 const int* __restrict__ idx2) {
    int b = blockIdx.y, n0 = blockIdx.x * NT, tid = threadIdx.x;
    __shared__ float4 T4[MM];        // 32KB
    __shared__ float wred[20][8];
    int r[NT][7]; float inv[NT][7];
    #pragma unroll
    for (int nt = 0; nt < NT; nt++) {
        const int* i1 = idx1 + ((size_t)b * NN + n0 + nt) * KK1;
        #pragma unroll
        for (int j = 0; j < 7; j++) {
            r[nt][j] = i1[j + 1];
            inv[nt][j] = g_rowinv[b * NN + r[nt][j]];
        }
    }
    const float* sb = g_scores + (size_t)b * NN * MM;
    for (int m = tid; m < MM; m += 256) {
        float4 t = {0.f, 0.f, 0.f, 0.f};
        #pragma unroll
        for (int j = 0; j < 7; j++) {
            t.x += sb[(size_t)r[0][j] * MM + m] * inv[0][j];
            t.y += sb[(size_t)r[1][j] * MM + m] * inv[1][j];
            t.z += sb[(size_t)r[2][j] * MM + m] * inv[2][j];
            t.w += sb[(size_t)r[3][j] * MM + m] * inv[3][j];
        }
        T4[m] = t;
    }
    __syncthreads();
    const int* ix2 = idx2 + (size_t)b * MM * KK1;
    const float* t0 = tgt + (size_t)b * 3 * MM;
    const float* d0 = g_dist + ((size_t)b * NN + n0) * MM;
    float sum[NT] = {}, c0[NT] = {}, c1[NT] = {}, c2[NT] = {};
    float mrf[NT] = {1e30f, 1e30f, 1e30f, 1e30f};
    for (int m = tid; m < MM; m += 256) {
        int4 qa = *(const int4*)(ix2 + (size_t)m * KK1);
        int4 qb = *(const int4*)(ix2 + (size_t)m * KK1 + 4);
        float4 S;
        {
            float4 v1 = T4[qa.y], v2 = T4[qa.z], v3 = T4[qa.w];
            float4 v4 = T4[qb.x], v5 = T4[qb.y], v6 = T4[qb.z], v7 = T4[qb.w];
            S.x = v1.x + v2.x + v3.x + v4.x + v5.x + v6.x + v7.x;
            S.y = v1.y + v2.y + v3.y + v4.y + v5.y + v6.y + v7.y;
            S.z = v1.z + v2.z + v3.z + v4.z + v5.z + v6.z + v7.z;
            S.w = v1.w + v2.w + v3.w + v4.w + v5.w + v6.w + v7.w;
        }
        float ty0 = t0[m], ty1 = t0[MM + m], ty2 = t0[2 * MM + m];
        const float* Sp = &S.x;
        #pragma unroll
        for (int nt = 0; nt < NT; nt++) {
            float d = d0[(size_t)nt * MM + m];
            float rf = expf(1.0f - Sp[nt] * (1.0f / 7.0f)) * d;
            float e = expf(-rf);
            sum[nt] += e;
            c0[nt] += ty0 * e; c1[nt] += ty1 * e; c2[nt] += ty2 * e;
            mrf[nt] = fminf(mrf[nt], rf);
        }
    }
    int lane = tid & 31, w = tid >> 5;
    #pragma unroll
    for (int nt = 0; nt < NT; nt++) {
        float v0 = sum[nt], v1 = c0[nt], v2 = c1[nt], v3 = c2[nt], v4 = mrf[nt];
        #pragma unroll
        for (int sh = 16; sh > 0; sh >>= 1) {
            v0 += __shfl_xor_sync(0xffffffffu, v0, sh);
            v1 += __shfl_xor_sync(0xffffffffu, v1, sh);
            v2 += __shfl_xor_sync(0xffffffffu, v2, sh);
            v3 += __shfl_xor_sync(0xffffffffu, v3, sh);
            v4 = fminf(v4, __shfl_xor_sync(0xffffffffu, v4, sh));
        }
        if (lane == 0) {
            wred[nt * 5 + 0][w] = v0; wred[nt * 5 + 1][w] = v1;
            wred[nt * 5 + 2][w] = v2; wred[nt * 5 + 3][w] = v3;
            wred[nt * 5 + 4][w] = v4;
        }
    }
    __syncthreads();
    if (tid < NT) {
        int nt = tid;
        float s = 0.f, a0 = 0.f, a1 = 0.f, a2 = 0.f, mn = 1e30f;
        #pragma unroll
        for (int j = 0; j < 8; j++) {
            s  += wred[nt * 5 + 0][j];
            a0 += wred[nt * 5 + 1][j];
            a1 += wred[nt * 5 + 2][j];
            a2 += wred[nt * 5 + 3][j];
            mn = fminf(mn, wred[nt * 5 + 4][j]);
        }
        float is = 1.f / s;
        int n = n0 + nt;
        g_corr[b * 3 * NN + n]          = a0 * is;
        g_corr[b * 3 * NN + NN + n]     = a1 * is;
        g_corr[b * 3 * NN + 2 * NN + n] = a2 * is;
        g_rowmax[b * NN + n] = expf(-mn) * is;
    }
}

// ================= K5: discriminator MLP + max over K =================
__global__ __launch_bounds__(128) void k_disc(const float* __restrict__ src,
                                              const float* __restrict__ src_knn,
                                              const int* __restrict__ src_idx,
                                              const float* __restrict__ W1, const float* __restrict__ b1,
                                              const float* __restrict__ W2, const float* __restrict__ b2,
                                              const float* __restrict__ W3, const float* __restrict__ b3) {
    __shared__ float W2s[H2D * H1D];
    __shared__ float W1s[H1D * 6];
    __shared__ float b1s[H1D];
    __shared__ float W3s[H2D];
    __shared__ float b2s[H2D];
    int tid = threadIdx.x;
    for (int i = tid; i < H2D * H1D; i += 128) W2s[i] = W2[i];
    for (int i = tid; i < H1D * 6; i += 128) W1s[i] = W1[i];
    if (tid < H1D) b1s[tid] = b1[tid];
    if (tid < H2D) { W3s[tid] = W3[tid]; b2s[tid] = b2[tid]; }
    __syncthreads();
    int gp = blockIdx.x * 8 + (tid >> 4);
    int b = gp / NN, n = gp % NN, kk = tid & 15;
    int id = src_idx[((size_t)b * NN + n) * KC + kk];
    const float* cb = g_corr + (size_t)b * 3 * NN;
    const float* sp = src + (size_t)b * 3 * NN;
    const float* skn = src_knn + (((size_t)b * NN + n) * KC + kk) * 3;
    float f[6];
    f[0] = cb[n] - cb[id];
    f[1] = cb[NN + n] - cb[NN + id];
    f[2] = cb[2 * NN + n] - cb[2 * NN + id];
    f[3] = sp[n] - skn[0];
    f[4] = sp[NN + n] - skn[1];
    f[5] = sp[2 * NN + n] - skn[2];
    float h1[H1D];
    #pragma unroll
    for (int d = 0; d < H1D; d++) {
        float a = b1s[d];
        #pragma unroll
        for (int c = 0; c < 6; c++) a += W1s[d * 6 + c] * f[c];
        h1[d] = fmaxf(a, 0.f);
    }
    float s = b3[0];
    for (int e = 0; e < H2D; e++) {
        float a = b2s[e];
        const float4* wr = (const float4*)&W2s[e * H1D];
        #pragma unroll
        for (int d4 = 0; d4 < H1D / 4; d4++) {
            float4 w = wr[d4];
            a += w.x * h1[d4 * 4] + w.y * h1[d4 * 4 + 1] + w.z * h1[d4 * 4 + 2] + w.w * h1[d4 * 4 + 3];
        }
        s += W3s[e] * fmaxf(a, 0.f);
    }
    #pragma unroll
    for (int o = 8; o > 0; o >>= 1) s = fmaxf(s, __shfl_xor_sync(0xffffffffu, s, o));
    if (kk == 0) g_slogit[b * NN + n] = s;
}

// ================= K6: softmax over N -> weight =================
__global__ __launch_bounds__(256) void k_wsoftmax() {
    int b = blockIdx.x, tid = threadIdx.x;
    __shared__ float red[256];
    float mx = -1e30f;
    for (int n = tid; n < NN; n += 256) mx = fmaxf(mx, g_slogit[b * NN + n]);
    red[tid] = mx; __syncthreads();
    for (int s = 128; s > 0; s >>= 1) { if (tid < s) red[tid] = fmaxf(red[tid], red[tid + s]); __syncthreads(); }
    mx = red[0]; __syncthreads();
    float sum = 0.f;
    for (int n = tid; n < NN; n += 256) sum += expf(g_slogit[b * NN + n] - mx);
    red[tid] = sum; __syncthreads();
    for (int s = 128; s > 0; s >>= 1) { if (tid < s) red[tid] += red[tid + s]; __syncthreads(); }
    float inv = 1.f / red[0];
    for (int n = tid; n < NN; n += 256) g_weight[b * NN + n] = expf(g_slogit[b * NN + n] - mx) * inv;
}

// ================= K7: rigid reduction + 3x3 SVD (Kabsch) =================
__device__ double det3d(const double M[3][3]) {
    return M[0][0]*(M[1][1]*M[2][2]-M[1][2]*M[2][1])
         - M[0][1]*(M[1][0]*M[2][2]-M[1][2]*M[2][0])
         + M[0][2]*(M[1][0]*M[2][1]-M[1][1]*M[2][0]);
}
__device__ void jacobi3(double a[3][3], double V[3][3], double w[3]) {
    for (int i = 0; i < 3; i++) for (int j = 0; j < 3; j++) V[i][j] = (i == j) ? 1.0 : 0.0;
    for (int sweep = 0; sweep < 15; sweep++) {
        const int ps[3] = {0, 0, 1}, qs[3] = {1, 2, 2};
        for (int rr = 0; rr < 3; rr++) {
            int p = ps[rr], q = qs[rr];
            double apq = a[p][q];
            if (fabs(apq) < 1e-300) continue;
            double theta = (a[q][q] - a[p][p]) / (2.0 * apq);
            double t = ((theta >= 0.0) ? 1.0 : -1.0) / (fabs(theta) + sqrt(theta * theta + 1.0));
            double c = 1.0 / sqrt(t * t + 1.0);
            double s = t * c;
            for (int k = 0; k < 3; k++) {
                double akp = a[k][p], akq = a[k][q];
                a[k][p] = c * akp - s * akq;
                a[k][q] = s * akp + c * akq;
            }
            for (int k = 0; k < 3; k++) {
                double apk = a[p][k], aqk = a[q][k];
                a[p][k] = c * apk - s * aqk;
                a[q][k] = s * apk + c * aqk;
            }
            for (int k = 0; k < 3; k++) {
                double vkp = V[k][p], vkq = V[k][q];
                V[k][p] = c * vkp - s * vkq;
                V[k][q] = s * vkp + c * vkq;
            }
        }
    }
    for (int i = 0; i < 3; i++) w[i] = a[i][i];
}
__global__ __launch_bounds__(256) void k_rigid(const float* __restrict__ src, float* __restrict__ out) {
    int b = blockIdx.x, tid = threadIdx.x;
    __shared__ float wp[16][8];
    __shared__ double res[16];
    const float* sp = src + (size_t)b * 3 * NN;
    const float* cb = g_corr + (size_t)b * 3 * NN;
    float acc[16] = {};
    for (int n = tid; n < NN; n += 256) {
        float w = g_weight[b * NN + n];
        float s0 = sp[n], s1 = sp[NN + n], s2 = sp[2 * NN + n];
        float c0 = cb[n], c1 = cb[NN + n], c2 = cb[2 * NN + n];
        acc[0] += w;
        acc[1] += w * s0; acc[2] += w * s1; acc[3] += w * s2;
        acc[4] += w * c0; acc[5] += w * c1; acc[6] += w * c2;
        acc[7]  += w * s0 * c0; acc[8]  += w * s0 * c1; acc[9]  += w * s0 * c2;
        acc[10] += w * s1 * c0; acc[11] += w * s1 * c1; acc[12] += w * s1 * c2;
        acc[13] += w * s2 * c0; acc[14] += w * s2 * c1; acc[15] += w * s2 * c2;
    }
    int lane = tid & 31, w8 = tid >> 5;
    #pragma unroll
    for (int q = 0; q < 16; q++) {
        float v = acc[q];
        #pragma unroll
        for (int sh = 16; sh > 0; sh >>= 1) v += __shfl_xor_sync(0xffffffffu, v, sh);
        if (lane == 0) wp[q][w8] = v;
    }
    __syncthreads();
    if (tid < 16) {
        double s = 0.0;
        for (int j = 0; j < 8; j++) s += (double)wp[tid][j];
        res[tid] = s;
    }
    __syncthreads();
    if (tid == 0) {
        double sw = res[0];
        double cs[3], ct[3], H[3][3];
        for (int i = 0; i < 3; i++) { cs[i] = res[1 + i] / sw; ct[i] = res[4 + i] / sw; }
        for (int i = 0; i < 3; i++)
            for (int j = 0; j < 3; j++)
                H[i][j] = res[7 + i * 3 + j] / sw - cs[i] * ct[j];
        double A[3][3];
        for (int i = 0; i < 3; i++)
            for (int j = 0; j < 3; j++) {
                double s = 0;
                for (int k = 0; k < 3; k++) s += H[k][i] * H[k][j];
                A[i][j] = s;
            }
        double V[3][3], wv[3];
        jacobi3(A, V, wv);
        for (int i = 0; i < 2; i++)
            for (int j = i + 1; j < 3; j++)
                if (wv[j] > wv[i]) {
                    double tw = wv[i]; wv[i] = wv[j]; wv[j] = tw;
                    for (int k = 0; k < 3; k++) { double tv = V[k][i]; V[k][i] = V[k][j]; V[k][j] = tv; }
                }
        double sig[3], U[3][3];
        for (int j = 0; j < 3; j++) sig[j] = sqrt(fmax(wv[j], 0.0));
        for (int j = 0; j < 3; j++) {
            double hv[3];
            for (int i = 0; i < 3; i++) {
                double s = 0;
                for (int k = 0; k < 3; k++) s += H[i][k] * V[k][j];
                hv[i] = s;
            }
            if (sig[j] > 1e-12 * fmax(sig[0], 1e-300)) {
                for (int i = 0; i < 3; i++) U[i][j] = hv[i] / sig[j];
            } else {
                U[0][j] = U[1][0] * U[2][1] - U[2][0] * U[1][1];
                U[1][j] = U[2][0] * U[0][1] - U[0][0] * U[2][1];
                U[2][j] = U[0][0] * U[1][1] - U[1][0] * U[0][1];
            }
        }
        double d = det3d(U) * det3d(V);
        double R[3][3];
        for (int i = 0; i < 3; i++)
            for (int k = 0; k < 3; k++)
                R[i][k] = V[i][0] * U[k][0] + V[i][1] * U[k][1] + d * V[i][2] * U[k][2];
        double tvec[3];
        for (int i = 0; i < 3; i++)
            tvec[i] = ct[i] - (R[i][0] * cs[0] + R[i][1] * cs[1] + R[i][2] * cs[2]);
        for (int i = 0; i < 3; i++) {
            for (int j = 0; j < 3; j++) {
                float rv = (float)R[i][j];
                g_R[b * 9 + i * 3 + j] = rv;
                out[OFF_R + b * 9 + i * 3 + j] = rv;
            }
            float tv = (float)tvec[i];
            g_t[b * 3 + i] = tv;
            out[OFF_T + b * 3 + i] = tv;
        }
    }
}

// ================= K8: stable top-k (rank by count), parallel =================
__global__ __launch_bounds__(256) void k_topk() {
    int b = blockIdx.x >> 4;
    int base = (blockIdx.x & 15) * 128;
    int tid = threadIdx.x;
    __shared__ float wsh[NN];
    for (int n = tid; n < NN; n += 256) wsh[n] = g_weight[b * NN + n];
    __syncthreads();
    int n = base + (tid >> 1);
    int half = tid & 1;
    float v = wsh[n];
    int rank = 0;
    int q0 = half * (NN / 2), q1 = q0 + NN / 2;
    for (int q = q0; q < q1; q++) {
        float u = wsh[q];
        rank += (u > v) || (u == v && q < n);
    }
    rank += __shfl_xor_sync(0xffffffffu, rank, 1);
    if (half == 0 && rank < KEY) g_topi[b * KEY + rank] = n;
}

// ================= K9: gather keypoints + knn outputs =================
__global__ __launch_bounds__(256) void k_outputs(const float* __restrict__ src,
                                                 const int* __restrict__ src_idx,
                                                 float* __restrict__ out) {
    int g = blockIdx.x * blockDim.x + threadIdx.x;
    if (g >= BB * KEY * KC) return;
    int kk = g % KC;
    int j = (g / KC) % KEY;
    int b = g / (KC * KEY);
    int tn = g_topi[b * KEY + j];
    const float* sp = src + (size_t)b * 3 * NN;
    const float* cb = g_corr + (size_t)b * 3 * NN;
    int id = src_idx[((size_t)b * NN + tn) * KC + kk];
    const float* R = g_R + b * 9;
    const float* tt = g_t + b * 3;
    float s0 = sp[tn], s1 = sp[NN + tn], s2 = sp[2 * NN + tn];
    float q0 = sp[id], q1 = sp[NN + id], q2 = sp[2 * NN + id];
    float st[3], sq[3];
    #pragma unroll
    for (int c = 0; c < 3; c++) {
        st[c] = R[c * 3] * s0 + R[c * 3 + 1] * s1 + R[c * 3 + 2] * s2 + tt[c];
        sq[c] = R[c * 3] * q0 + R[c * 3 + 1] * q1 + R[c * 3 + 2] * q2 + tt[c];
    }
    float* skk = out + OFF_SKNN;
    float* tkk = out + OFF_TKNN;
    #pragma unroll
    for (int c = 0; c < 3; c++) {
        size_t o = (((size_t)b * 3 + c) * KEY + j) * KC + kk;
        skk[o] = st[c] - sq[c];
        tkk[o] = cb[c * NN + tn] - cb[c * NN + id];
    }
    if (kk == 0) {
        float* skp = out + OFF_SKP;
        float* tkp = out + OFF_TKP;
        #pragma unroll
        for (int c = 0; c < 3; c++) {
            skp[((size_t)b * 3 + c) * KEY + j] = sp[c * NN + tn];
            tkp[((size_t)b * 3 + c) * KEY + j] = cb[c * NN + tn];
        }
    }
}

// ================= K10: loss =================
__global__ __launch_bounds__(256) void k_loss(float* __restrict__ out) {
    __shared__ double red[256];
    int tid = threadIdx.x;
    double s = 0.0;
    for (int p = tid; p < BB * KEY; p += 256) {
        int b = p / KEY;
        int tn = g_topi[p];
        double pm = (double)g_rowmax[b * NN + tn];
        s += -log(pm + 1e-15);
    }
    red[tid] = s; __syncthreads();
    for (int st = 128; st > 0; st >>= 1) { if (tid < st) red[tid] += red[tid + st]; __syncthreads(); }
    if (tid == 0) out[OFF_LOSS] = (float)(red[0] / (double)(BB * KEY));
}

// ================= launch =================
extern "C" void kernel_launch(void* const* d_in, const int* in_sizes, int n_in,
                              void* d_out, int out_size) {
    const float* src      = (const float*)d_in[0];
    const float* tgt      = (const float*)d_in[1];
    const float* se       = (const float*)d_in[2];
    const float* te       = (const float*)d_in[3];
    const float* src_knn  = (const float*)d_in[4];
    const float* W1 = (const float*)d_in[6];
    const float* b1 = (const float*)d_in[7];
    const float* W2 = (const float*)d_in[8];
    const float* b2 = (const float*)d_in[9];
    const float* W3 = (const float*)d_in[10];
    const float* b3 = (const float*)d_in[11];
    const int* src_idx  = (const int*)d_in[12];
    const int* src_idx1 = (const int*)d_in[13];
    const int* idx2     = (const int*)d_in[14];
    float* out = (float*)d_out;

    const int smem_gemm = 2 * STAGE_E * (int)sizeof(__nv_bfloat16);  // 122880 B
    cudaFuncSetAttribute(k_gemm, cudaFuncAttributeMaxDynamicSharedMemorySize, smem_gemm);

    dim3 gp(CC / 32, NN / 32, 2 * BB);
    k_prep<<<gp, 256>>>(se, te);
    k_norms<<<(BB * NN + BB * MM) / 256, 256>>>(se, te);
    dim3 gg(MM / 128, NN / 128, BB);
    k_gemm<<<gg, 256, smem_gemm>>>();
    k_invsum<<<(BB * NN * 32 + 255) / 256, 256>>>();
    dim3 gr(NN / NT, BB);
    k_rowpipe<<<gr, 256>>>(tgt, src_idx1, idx2);
    k_disc<<<BB * NN / 8, 128>>>(src, src_knn, src_idx, W1, b1, W2, b2, W3, b3);
    k_wsoftmax<<<BB, 256>>>();
    k_rigid<<<BB, 256>>>(src, out);
    k_topk<<<BB * 16, 256>>>();
    k_outputs<<<(BB * KEY * KC + 255) / 256, 256>>>(src, src_idx, out);
    k_loss<<<1, 256>>>(out);
}

// round 15
// speedup vs baseline: 1.8919x; 1.0757x over previous
#include <cuda_runtime.h>
#include <cuda_bf16.h>
#include <math.h>
#include <stdint.h>

#define BB 2
#define NN 2048
#define MM 2048
#define CC 512
#define KC 16        // K
#define KK1 8        // K1
#define KEY 1024
#define H1D 64
#define H2D 128

// ---------------- device scratch (no allocs allowed) ----------------
__device__ float g_scores[BB * NN * MM];   // 33.5 MB (unnormalized e = exp(-dist))
__device__ float g_xx[BB * NN];
__device__ float g_yy[BB * MM];
__device__ float g_rowpart[BB * NN * 64];  // per (row, m-block*2 + warp_n) partial sums of e
__device__ float g_rowinv[BB * NN];        // 1 / row sum of e
__device__ float g_corr[BB * 3 * NN];      // src_corr (B,3,N)
__device__ float g_rowmax[BB * NN];        // max of rmm row
__device__ float g_slogit[BB * NN];
__device__ float g_weight[BB * NN];
__device__ int   g_topi[BB * KEY];
__device__ float g_R[BB * 9];
__device__ float g_t[BB * 3];
// bf16 3-way split operands, K-major [b][n][c]
__device__ __nv_bfloat16 g_A1[BB * NN * CC];
__device__ __nv_bfloat16 g_A2[BB * NN * CC];
__device__ __nv_bfloat16 g_A3[BB * NN * CC];
__device__ __nv_bfloat16 g_B1[BB * MM * CC];
__device__ __nv_bfloat16 g_B2[BB * MM * CC];
__device__ __nv_bfloat16 g_B3[BB * MM * CC];

// ---------------- output layout offsets (fp32, tuple order) ----------------
#define OFF_R     0
#define OFF_T     18
#define OFF_SKP   24
#define OFF_TKP   (24 + BB*3*KEY)
#define OFF_SKNN  (OFF_TKP + BB*3*KEY)
#define OFF_TKNN  (OFF_SKNN + BB*3*KEY*KC)
#define OFF_LOSS  (OFF_TKNN + BB*3*KEY*KC)

// ---------------- warp mma + cp.async helpers (compute_103-safe) ----------
__device__ __forceinline__ uint32_t smem_u32(const void* p) {
    uint32_t a;
    asm("{ .reg .u64 t; cvta.to.shared.u64 t, %1; cvt.u32.u64 %0, t; }" : "=r"(a) : "l"(p));
    return a;
}
__device__ __forceinline__ void ldsm4(uint32_t* r, uint32_t addr) {
    asm volatile("ldmatrix.sync.aligned.m8n8.x4.shared.b16 {%0,%1,%2,%3}, [%4];"
        : "=r"(r[0]), "=r"(r[1]), "=r"(r[2]), "=r"(r[3]) : "r"(addr));
}
__device__ __forceinline__ void ldsm2(uint32_t* r, uint32_t addr) {
    asm volatile("ldmatrix.sync.aligned.m8n8.x2.shared.b16 {%0,%1}, [%2];"
        : "=r"(r[0]), "=r"(r[1]) : "r"(addr));
}
__device__ __forceinline__ void mma16816(float* d, const uint32_t* a, const uint32_t* b) {
    asm volatile(
        "mma.sync.aligned.m16n8k16.row.col.f32.bf16.bf16.f32 "
        "{%0,%1,%2,%3}, {%4,%5,%6,%7}, {%8,%9}, {%0,%1,%2,%3};"
        : "+f"(d[0]), "+f"(d[1]), "+f"(d[2]), "+f"(d[3])
        : "r"(a[0]), "r"(a[1]), "r"(a[2]), "r"(a[3]), "r"(b[0]), "r"(b[1]));
}
__device__ __forceinline__ void cp16(uint32_t saddr, const void* gaddr) {
    asm volatile("cp.async.cg.shared.global [%0], [%1], 16;" :: "r"(saddr), "l"(gaddr));
}
#define CP_COMMIT() asm volatile("cp.async.commit_group;" ::: "memory")
#define CP_WAIT0()  asm volatile("cp.async.wait_group 0;" ::: "memory")

// ================= K0: transpose + 3-way bf16 split prep =================
__global__ __launch_bounds__(256) void k_prep(const float* __restrict__ se,
                                              const float* __restrict__ te) {
    __shared__ float t[32][33];
    int zb = blockIdx.z;
    const float* src = (zb < BB) ? se + (size_t)zb * CC * NN : te + (size_t)(zb - BB) * CC * NN;
    __nv_bfloat16* p1 = (zb < BB) ? g_A1 + (size_t)zb * NN * CC : g_B1 + (size_t)(zb - BB) * NN * CC;
    __nv_bfloat16* p2 = (zb < BB) ? g_A2 + (size_t)zb * NN * CC : g_B2 + (size_t)(zb - BB) * NN * CC;
    __nv_bfloat16* p3 = (zb < BB) ? g_A3 + (size_t)zb * NN * CC : g_B3 + (size_t)(zb - BB) * NN * CC;
    int c0 = blockIdx.x * 32, n0 = blockIdx.y * 32;
    int tx = threadIdx.x & 31, ty = threadIdx.x >> 5;
    #pragma unroll
    for (int i = 0; i < 4; i++)
        t[ty + i * 8][tx] = src[(size_t)(c0 + ty + i * 8) * NN + n0 + tx];
    __syncthreads();
    #pragma unroll
    for (int i = 0; i < 4; i++) {
        int n = n0 + ty + i * 8, c = c0 + tx;
        float v = t[tx][ty + i * 8];
        __nv_bfloat16 h1 = __float2bfloat16(v);
        float r1 = v - __bfloat162float(h1);
        __nv_bfloat16 h2 = __float2bfloat16(r1);
        float r2 = r1 - __bfloat162float(h2);
        __nv_bfloat16 h3 = __float2bfloat16(r2);
        p1[(size_t)n * CC + c] = h1;
        p2[(size_t)n * CC + c] = h2;
        p3[(size_t)n * CC + c] = h3;
    }
}

// ================= K1: column squared norms =================
__global__ void k_norms(const float* __restrict__ se, const float* __restrict__ te) {
    int col = blockIdx.x * blockDim.x + threadIdx.x;
    if (col < BB * NN) {
        int b = col / NN, n = col % NN;
        const float* p = se + (size_t)b * CC * NN + n;
        float s = 0.f;
        for (int c = 0; c < CC; c++) { float v = p[(size_t)c * NN]; s += v * v; }
        g_xx[col] = s;
    } else {
        int c2 = col - BB * NN;
        if (c2 < BB * MM) {
            int b = c2 / MM, m = c2 % MM;
            const float* p = te + (size_t)b * CC * MM + m;
            float s = 0.f;
            for (int c = 0; c < CC; c++) { float v = p[(size_t)c * MM]; s += v * v; }
            g_yy[c2] = s;
        }
    }
}

// ================= K2: bf16x6 HMMA GEMM, cp.async double-buffered, 2 CTA/SM
// grid (MM/64, NN/128, BB), block 256 (8 warps: 4 warp_m x 2 warp_n; warp tile 32x32)
#define RSB 40                       // smem row stride in bf16 (80B, conflict-free)
#define TILE_A (128 * RSB)           // A operand tile elements (128 rows)
#define TILE_B (64 * RSB)            // B operand tile elements (64 rows)
#define STAGE_E (3 * TILE_A + 3 * TILE_B)   // 23040 elements = 46080 B
__global__ __launch_bounds__(256, 2) void k_gemm() {
    extern __shared__ __align__(16) __nv_bfloat16 sm[];   // 2 stages
    __shared__ float yys[64];

    int tid = threadIdx.x;
    int wid = tid >> 5, lane = tid & 31;
    int warp_m = wid >> 1, warp_n = wid & 1;
    int b = blockIdx.z;
    int m0 = blockIdx.x * 64, n0 = blockIdx.y * 128;

    const __nv_bfloat16* pA[3];
    const __nv_bfloat16* pB[3];
    pA[0] = g_A1 + ((size_t)b * NN + n0) * CC;
    pA[1] = g_A2 + ((size_t)b * NN + n0) * CC;
    pA[2] = g_A3 + ((size_t)b * NN + n0) * CC;
    pB[0] = g_B1 + ((size_t)b * MM + m0) * CC;
    pB[1] = g_B2 + ((size_t)b * MM + m0) * CC;
    pB[2] = g_B3 + ((size_t)b * MM + m0) * CC;

    if (tid < 64) yys[tid] = g_yy[b * MM + m0 + tid];

    float acc[2][4][4];
    #pragma unroll
    for (int mi = 0; mi < 2; mi++)
        #pragma unroll
        for (int ni = 0; ni < 4; ni++)
            #pragma unroll
            for (int q = 0; q < 4; q++) acc[mi][ni][q] = 0.f;

    uint32_t smb = smem_u32(sm);
    int ldrow = tid >> 2, ldseg = tid & 3;   // 64 rows per pass, 4x16B segs

    // per-tile element offsets within a stage
    const uint32_t offA[3] = {0, TILE_A, 2 * TILE_A};
    const uint32_t offB[3] = {3 * TILE_A, 3 * TILE_A + TILE_B, 3 * TILE_A + 2 * TILE_B};

    uint32_t aoff = (lane & 15) * (RSB * 2) + (lane >> 4) * 16 + warp_m * 32 * (RSB * 2);
    uint32_t boff = (lane & 7) * (RSB * 2) + ((lane >> 3) & 1) * 16 + warp_n * 32 * (RSB * 2);

    // ---- prefetch stage 0 ----
    #pragma unroll
    for (int t = 0; t < 3; t++) {
        #pragma unroll
        for (int i = 0; i < 2; i++) {
            int row = ldrow + i * 64;
            cp16(smb + (offA[t] + (uint32_t)(row * RSB + ldseg * 8)) * 2,
                 pA[t] + (size_t)row * CC + ldseg * 8);
        }
        cp16(smb + (offB[t] + (uint32_t)(ldrow * RSB + ldseg * 8)) * 2,
             pB[t] + (size_t)ldrow * CC + ldseg * 8);
    }
    CP_COMMIT();

    for (int kc = 0; kc < CC / 32; kc++) {
        CP_WAIT0();
        __syncthreads();
        uint32_t stage = (uint32_t)(kc & 1) * STAGE_E * 2;   // byte offset
        if (kc + 1 < CC / 32) {
            uint32_t nst = (uint32_t)((kc + 1) & 1) * STAGE_E * 2;
            int kn = (kc + 1) * 32;
            #pragma unroll
            for (int t = 0; t < 3; t++) {
                #pragma unroll
                for (int i = 0; i < 2; i++) {
                    int row = ldrow + i * 64;
                    cp16(smb + nst + (offA[t] + (uint32_t)(row * RSB + ldseg * 8)) * 2,
                         pA[t] + (size_t)row * CC + kn + ldseg * 8);
                }
                cp16(smb + nst + (offB[t] + (uint32_t)(ldrow * RSB + ldseg * 8)) * 2,
                     pB[t] + (size_t)ldrow * CC + kn + ldseg * 8);
            }
            CP_COMMIT();
        }
        uint32_t a1b = smb + stage + offA[0] * 2 + aoff;
        uint32_t a2b = smb + stage + offA[1] * 2 + aoff;
        uint32_t a3b = smb + stage + offA[2] * 2 + aoff;
        uint32_t b1b = smb + stage + offB[0] * 2 + boff;
        uint32_t b2b = smb + stage + offB[1] * 2 + boff;
        uint32_t b3b = smb + stage + offB[2] * 2 + boff;
        #pragma unroll
        for (int ks = 0; ks < 2; ks++) {
            uint32_t a1[2][4], a2[2][4], a3[2][4], bf[4][2];
            uint32_t kso = ks * 32;
            #pragma unroll
            for (int mi = 0; mi < 2; mi++) {
                ldsm4(a1[mi], a1b + mi * 16 * (RSB * 2) + kso);
                ldsm4(a2[mi], a2b + mi * 16 * (RSB * 2) + kso);
                ldsm4(a3[mi], a3b + mi * 16 * (RSB * 2) + kso);
            }
            #pragma unroll
            for (int ni = 0; ni < 4; ni++)
                ldsm2(bf[ni], b1b + ni * 8 * (RSB * 2) + kso);
            #pragma unroll
            for (int mi = 0; mi < 2; mi++)
                #pragma unroll
                for (int ni = 0; ni < 4; ni++) {
                    mma16816(acc[mi][ni], a1[mi], bf[ni]);
                    mma16816(acc[mi][ni], a2[mi], bf[ni]);
                    mma16816(acc[mi][ni], a3[mi], bf[ni]);
                }
            #pragma unroll
            for (int ni = 0; ni < 4; ni++)
                ldsm2(bf[ni], b2b + ni * 8 * (RSB * 2) + kso);
            #pragma unroll
            for (int mi = 0; mi < 2; mi++)
                #pragma unroll
                for (int ni = 0; ni < 4; ni++) {
                    mma16816(acc[mi][ni], a1[mi], bf[ni]);
                    mma16816(acc[mi][ni], a2[mi], bf[ni]);
                }
            #pragma unroll
            for (int ni = 0; ni < 4; ni++)
                ldsm2(bf[ni], b3b + ni * 8 * (RSB * 2) + kso);
            #pragma unroll
            for (int mi = 0; mi < 2; mi++)
                #pragma unroll
                for (int ni = 0; ni < 4; ni++) mma16816(acc[mi][ni], a1[mi], bf[ni]);
        }
    }
    __syncthreads();

    // ---- epilogue: dist = xx - 2*dot + yy ; store e = exp(-dist) ; row partials
    int l4 = lane & 3, l2 = lane >> 2;
    int n_base = n0 + warp_m * 32;
    size_t gb = (size_t)b * NN * MM;
    #pragma unroll
    for (int mi = 0; mi < 2; mi++) {
        #pragma unroll
        for (int half = 0; half < 2; half++) {
            int r = mi * 16 + half * 8 + l2;
            int n = n_base + r;
            float xv = g_xx[b * NN + n];
            float rs = 0.f;
            size_t rowo = gb + (size_t)n * MM + m0 + warp_n * 32;
            #pragma unroll
            for (int ni = 0; ni < 4; ni++) {
                int mc = ni * 8 + l4 * 2;
                float v0 = acc[mi][ni][half * 2 + 0];
                float v1 = acc[mi][ni][half * 2 + 1];
                float d0 = xv - 2.f * v0 + yys[warp_n * 32 + mc];
                float d1 = xv - 2.f * v1 + yys[warp_n * 32 + mc + 1];
                float e0 = expf(-d0), e1 = expf(-d1);
                *(float2*)&g_scores[rowo + mc] = make_float2(e0, e1);
                rs += e0 + e1;
            }
            rs += __shfl_xor_sync(0xffffffffu, rs, 1);
            rs += __shfl_xor_sync(0xffffffffu, rs, 2);
            if (l4 == 0)
                g_rowpart[((size_t)b * NN + n) * 64 + blockIdx.x * 2 + warp_n] = rs;
        }
    }
}

// ================= K3: finalize row inverse sums (warp per row) =========
__global__ __launch_bounds__(256) void k_invsum() {
    int w = (blockIdx.x * 256 + threadIdx.x) >> 5;   // row index
    int lane = threadIdx.x & 31;
    if (w < BB * NN) {
        const float* p = g_rowpart + (size_t)w * 64;
        float s = p[lane] + p[lane + 32];
        #pragma unroll
        for (int sh = 16; sh > 0; sh >>= 1) s += __shfl_xor_sync(0xffffffffu, s, sh);
        if (lane == 0) g_rowinv[w] = 1.f / s;
    }
}

// ================= K4: per-row T/S/refined/rmm pipeline (NT=4) =================
#define NT 4
__global__ __launch_bounds__(256) void k_rowpipe(const float* __restrict__ tgt,
                                                 const int* __restrict__ idx1,
                                                 const int* __restrict__ idx2) {
    int b = blockIdx.y, n0 = blockIdx.x * NT, tid = threadIdx.x;
    __shared__ float4 T4[MM];        // 32KB
    __shared__ float wred[20][8];
    int r[NT][7]; float inv[NT][7];
    #pragma unroll
    for (int nt = 0; nt < NT; nt++) {
        const int* i1 = idx1 + ((size_t)b * NN + n0 + nt) * KK1;
        #pragma unroll
        for (int j = 0; j < 7; j++) {
            r[nt][j] = i1[j + 1];
            inv[nt][j] = g_rowinv[b * NN + r[nt][j]];
        }
    }
    const float* sb = g_scores + (size_t)b * NN * MM;
    for (int m = tid; m < MM; m += 256) {
        float4 t = {0.f, 0.f, 0.f, 0.f};
        #pragma unroll
        for (int j = 0; j < 7; j++) {
            t.x += sb[(size_t)r[0][j] * MM + m] * inv[0][j];
            t.y += sb[(size_t)r[1][j] * MM + m] * inv[1][j];
            t.z += sb[(size_t)r[2][j] * MM + m] * inv[2][j];
            t.w += sb[(size_t)r[3][j] * MM + m] * inv[3][j];
        }
        T4[m] = t;
    }
    __syncthreads();
    const int* ix2 = idx2 + (size_t)b * MM * KK1;
    const float* t0 = tgt + (size_t)b * 3 * MM;
    const float* s0 = sb + (size_t)n0 * MM;
    float sum[NT] = {}, c0[NT] = {}, c1[NT] = {}, c2[NT] = {};
    float mrf[NT] = {1e30f, 1e30f, 1e30f, 1e30f};
    for (int m = tid; m < MM; m += 256) {
        int4 qa = *(const int4*)(ix2 + (size_t)m * KK1);
        int4 qb = *(const int4*)(ix2 + (size_t)m * KK1 + 4);
        float4 S;
        {
            float4 v1 = T4[qa.y], v2 = T4[qa.z], v3 = T4[qa.w];
            float4 v4 = T4[qb.x], v5 = T4[qb.y], v6 = T4[qb.z], v7 = T4[qb.w];
            S.x = v1.x + v2.x + v3.x + v4.x + v5.x + v6.x + v7.x;
            S.y = v1.y + v2.y + v3.y + v4.y + v5.y + v6.y + v7.y;
            S.z = v1.z + v2.z + v3.z + v4.z + v5.z + v6.z + v7.z;
            S.w = v1.w + v2.w + v3.w + v4.w + v5.w + v6.w + v7.w;
        }
        float ty0 = t0[m], ty1 = t0[MM + m], ty2 = t0[2 * MM + m];
        const float* Sp = &S.x;
        #pragma unroll
        for (int nt = 0; nt < NT; nt++) {
            float ein = s0[(size_t)nt * MM + m];
            float d = -logf(ein);                    // recover dist
            float rf = expf(1.0f - Sp[nt] * (1.0f / 7.0f)) * d;
            float e = expf(-rf);
            sum[nt] += e;
            c0[nt] += ty0 * e; c1[nt] += ty1 * e; c2[nt] += ty2 * e;
            mrf[nt] = fminf(mrf[nt], rf);
        }
    }
    int lane = tid & 31, w = tid >> 5;
    #pragma unroll
    for (int nt = 0; nt < NT; nt++) {
        float v0 = sum[nt], v1 = c0[nt], v2 = c1[nt], v3 = c2[nt], v4 = mrf[nt];
        #pragma unroll
        for (int sh = 16; sh > 0; sh >>= 1) {
            v0 += __shfl_xor_sync(0xffffffffu, v0, sh);
            v1 += __shfl_xor_sync(0xffffffffu, v1, sh);
            v2 += __shfl_xor_sync(0xffffffffu, v2, sh);
            v3 += __shfl_xor_sync(0xffffffffu, v3, sh);
            v4 = fminf(v4, __shfl_xor_sync(0xffffffffu, v4, sh));
        }
        if (lane == 0) {
            wred[nt * 5 + 0][w] = v0; wred[nt * 5 + 1][w] = v1;
            wred[nt * 5 + 2][w] = v2; wred[nt * 5 + 3][w] = v3;
            wred[nt * 5 + 4][w] = v4;
        }
    }
    __syncthreads();
    if (tid < NT) {
        int nt = tid;
        float s = 0.f, a0 = 0.f, a1 = 0.f, a2 = 0.f, mn = 1e30f;
        #pragma unroll
        for (int j = 0; j < 8; j++) {
            s  += wred[nt * 5 + 0][j];
            a0 += wred[nt * 5 + 1][j];
            a1 += wred[nt * 5 + 2][j];
            a2 += wred[nt * 5 + 3][j];
            mn = fminf(mn, wred[nt * 5 + 4][j]);
        }
        float is = 1.f / s;
        int n = n0 + nt;
        g_corr[b * 3 * NN + n]          = a0 * is;
        g_corr[b * 3 * NN + NN + n]     = a1 * is;
        g_corr[b * 3 * NN + 2 * NN + n] = a2 * is;
        g_rowmax[b * NN + n] = expf(-mn) * is;
    }
}

// ================= K5: discriminator MLP + max over K =================
__global__ __launch_bounds__(128) void k_disc(const float* __restrict__ src,
                                              const float* __restrict__ src_knn,
                                              const int* __restrict__ src_idx,
                                              const float* __restrict__ W1, const float* __restrict__ b1,
                                              const float* __restrict__ W2, const float* __restrict__ b2,
                                              const float* __restrict__ W3, const float* __restrict__ b3) {
    __shared__ float W2s[H2D * H1D];
    __shared__ float W1s[H1D * 6];
    __shared__ float b1s[H1D];
    __shared__ float W3s[H2D];
    __shared__ float b2s[H2D];
    int tid = threadIdx.x;
    for (int i = tid; i < H2D * H1D; i += 128) W2s[i] = W2[i];
    for (int i = tid; i < H1D * 6; i += 128) W1s[i] = W1[i];
    if (tid < H1D) b1s[tid] = b1[tid];
    if (tid < H2D) { W3s[tid] = W3[tid]; b2s[tid] = b2[tid]; }
    __syncthreads();
    int gp = blockIdx.x * 8 + (tid >> 4);
    int b = gp / NN, n = gp % NN, kk = tid & 15;
    int id = src_idx[((size_t)b * NN + n) * KC + kk];
    const float* cb = g_corr + (size_t)b * 3 * NN;
    const float* sp = src + (size_t)b * 3 * NN;
    const float* skn = src_knn + (((size_t)b * NN + n) * KC + kk) * 3;
    float f[6];
    f[0] = cb[n] - cb[id];
    f[1] = cb[NN + n] - cb[NN + id];
    f[2] = cb[2 * NN + n] - cb[2 * NN + id];
    f[3] = sp[n] - skn[0];
    f[4] = sp[NN + n] - skn[1];
    f[5] = sp[2 * NN + n] - skn[2];
    float h1[H1D];
    #pragma unroll
    for (int d = 0; d < H1D; d++) {
        float a = b1s[d];
        #pragma unroll
        for (int c = 0; c < 6; c++) a += W1s[d * 6 + c] * f[c];
        h1[d] = fmaxf(a, 0.f);
    }
    float s = b3[0];
    for (int e = 0; e < H2D; e++) {
        float a = b2s[e];
        const float4* wr = (const float4*)&W2s[e * H1D];
        #pragma unroll
        for (int d4 = 0; d4 < H1D / 4; d4++) {
            float4 w = wr[d4];
            a += w.x * h1[d4 * 4] + w.y * h1[d4 * 4 + 1] + w.z * h1[d4 * 4 + 2] + w.w * h1[d4 * 4 + 3];
        }
        s += W3s[e] * fmaxf(a, 0.f);
    }
    #pragma unroll
    for (int o = 8; o > 0; o >>= 1) s = fmaxf(s, __shfl_xor_sync(0xffffffffu, s, o));
    if (kk == 0) g_slogit[b * NN + n] = s;
}

// ================= K6: softmax over N -> weight =================
__global__ __launch_bounds__(256) void k_wsoftmax() {
    int b = blockIdx.x, tid = threadIdx.x;
    __shared__ float red[256];
    float mx = -1e30f;
    for (int n = tid; n < NN; n += 256) mx = fmaxf(mx, g_slogit[b * NN + n]);
    red[tid] = mx; __syncthreads();
    for (int s = 128; s > 0; s >>= 1) { if (tid < s) red[tid] = fmaxf(red[tid], red[tid + s]); __syncthreads(); }
    mx = red[0]; __syncthreads();
    float sum = 0.f;
    for (int n = tid; n < NN; n += 256) sum += expf(g_slogit[b * NN + n] - mx);
    red[tid] = sum; __syncthreads();
    for (int s = 128; s > 0; s >>= 1) { if (tid < s) red[tid] += red[tid + s]; __syncthreads(); }
    float inv = 1.f / red[0];
    for (int n = tid; n < NN; n += 256) g_weight[b * NN + n] = expf(g_slogit[b * NN + n] - mx) * inv;
}

// ================= K7: rigid reduction + 3x3 SVD (Kabsch) =================
__device__ double det3d(const double M[3][3]) {
    return M[0][0]*(M[1][1]*M[2][2]-M[1][2]*M[2][1])
         - M[0][1]*(M[1][0]*M[2][2]-M[1][2]*M[2][0])
         + M[0][2]*(M[1][0]*M[2][1]-M[1][1]*M[2][0]);
}
__device__ void jacobi3(double a[3][3], double V[3][3], double w[3]) {
    for (int i = 0; i < 3; i++) for (int j = 0; j < 3; j++) V[i][j] = (i == j) ? 1.0 : 0.0;
    for (int sweep = 0; sweep < 15; sweep++) {
        const int ps[3] = {0, 0, 1}, qs[3] = {1, 2, 2};
        for (int rr = 0; rr < 3; rr++) {
            int p = ps[rr], q = qs[rr];
            double apq = a[p][q];
            if (fabs(apq) < 1e-300) continue;
            double theta = (a[q][q] - a[p][p]) / (2.0 * apq);
            double t = ((theta >= 0.0) ? 1.0 : -1.0) / (fabs(theta) + sqrt(theta * theta + 1.0));
            double c = 1.0 / sqrt(t * t + 1.0);
            double s = t * c;
            for (int k = 0; k < 3; k++) {
                double akp = a[k][p], akq = a[k][q];
                a[k][p] = c * akp - s * akq;
                a[k][q] = s * akp + c * akq;
            }
            for (int k = 0; k < 3; k++) {
                double apk = a[p][k], aqk = a[q][k];
                a[p][k] = c * apk - s * aqk;
                a[q][k] = s * apk + c * aqk;
            }
            for (int k = 0; k < 3; k++) {
                double vkp = V[k][p], vkq = V[k][q];
                V[k][p] = c * vkp - s * vkq;
                V[k][q] = s * vkp + c * vkq;
            }
        }
    }
    for (int i = 0; i < 3; i++) w[i] = a[i][i];
}
__global__ __launch_bounds__(256) void k_rigid(const float* __restrict__ src, float* __restrict__ out) {
    int b = blockIdx.x, tid = threadIdx.x;
    __shared__ float wp[16][8];
    __shared__ double res[16];
    const float* sp = src + (size_t)b * 3 * NN;
    const float* cb = g_corr + (size_t)b * 3 * NN;
    float acc[16] = {};
    for (int n = tid; n < NN; n += 256) {
        float w = g_weight[b * NN + n];
        float s0 = sp[n], s1 = sp[NN + n], s2 = sp[2 * NN + n];
        float c0 = cb[n], c1 = cb[NN + n], c2 = cb[2 * NN + n];
        acc[0] += w;
        acc[1] += w * s0; acc[2] += w * s1; acc[3] += w * s2;
        acc[4] += w * c0; acc[5] += w * c1; acc[6] += w * c2;
        acc[7]  += w * s0 * c0; acc[8]  += w * s0 * c1; acc[9]  += w * s0 * c2;
        acc[10] += w * s1 * c0; acc[11] += w * s1 * c1; acc[12] += w * s1 * c2;
        acc[13] += w * s2 * c0; acc[14] += w * s2 * c1; acc[15] += w * s2 * c2;
    }
    int lane = tid & 31, w8 = tid >> 5;
    #pragma unroll
    for (int q = 0; q < 16; q++) {
        float v = acc[q];
        #pragma unroll
        for (int sh = 16; sh > 0; sh >>= 1) v += __shfl_xor_sync(0xffffffffu, v, sh);
        if (lane == 0) wp[q][w8] = v;
    }
    __syncthreads();
    if (tid < 16) {
        double s = 0.0;
        for (int j = 0; j < 8; j++) s += (double)wp[tid][j];
        res[tid] = s;
    }
    __syncthreads();
    if (tid == 0) {
        double sw = res[0];
        double cs[3], ct[3], H[3][3];
        for (int i = 0; i < 3; i++) { cs[i] = res[1 + i] / sw; ct[i] = res[4 + i] / sw; }
        for (int i = 0; i < 3; i++)
            for (int j = 0; j < 3; j++)
                H[i][j] = res[7 + i * 3 + j] / sw - cs[i] * ct[j];
        double A[3][3];
        for (int i = 0; i < 3; i++)
            for (int j = 0; j < 3; j++) {
                double s = 0;
                for (int k = 0; k < 3; k++) s += H[k][i] * H[k][j];
                A[i][j] = s;
            }
        double V[3][3], wv[3];
        jacobi3(A, V, wv);
        for (int i = 0; i < 2; i++)
            for (int j = i + 1; j < 3; j++)
                if (wv[j] > wv[i]) {
                    double tw = wv[i]; wv[i] = wv[j]; wv[j] = tw;
                    for (int k = 0; k < 3; k++) { double tv = V[k][i]; V[k][i] = V[k][j]; V[k][j] = tv; }
                }
        double sig[3], U[3][3];
        for (int j = 0; j < 3; j++) sig[j] = sqrt(fmax(wv[j], 0.0));
        for (int j = 0; j < 3; j++) {
            double hv[3];
            for (int i = 0; i < 3; i++) {
                double s = 0;
                for (int k = 0; k < 3; k++) s += H[i][k] * V[k][j];
                hv[i] = s;
            }
            if (sig[j] > 1e-12 * fmax(sig[0], 1e-300)) {
                for (int i = 0; i < 3; i++) U[i][j] = hv[i] / sig[j];
            } else {
                U[0][j] = U[1][0] * U[2][1] - U[2][0] * U[1][1];
                U[1][j] = U[2][0] * U[0][1] - U[0][0] * U[2][1];
                U[2][j] = U[0][0] * U[1][1] - U[1][0] * U[0][1];
            }
        }
        double d = det3d(U) * det3d(V);
        double R[3][3];
        for (int i = 0; i < 3; i++)
            for (int k = 0; k < 3; k++)
                R[i][k] = V[i][0] * U[k][0] + V[i][1] * U[k][1] + d * V[i][2] * U[k][2];
        double tvec[3];
        for (int i = 0; i < 3; i++)
            tvec[i] = ct[i] - (R[i][0] * cs[0] + R[i][1] * cs[1] + R[i][2] * cs[2]);
        for (int i = 0; i < 3; i++) {
            for (int j = 0; j < 3; j++) {
                float rv = (float)R[i][j];
                g_R[b * 9 + i * 3 + j] = rv;
                out[OFF_R + b * 9 + i * 3 + j] = rv;
            }
            float tv = (float)tvec[i];
            g_t[b * 3 + i] = tv;
            out[OFF_T + b * 3 + i] = tv;
        }
    }
}

// ================= K8: stable top-k (rank by count), parallel =================
__global__ __launch_bounds__(256) void k_topk() {
    int b = blockIdx.x >> 4;
    int base = (blockIdx.x & 15) * 128;
    int tid = threadIdx.x;
    __shared__ float wsh[NN];
    for (int n = tid; n < NN; n += 256) wsh[n] = g_weight[b * NN + n];
    __syncthreads();
    int n = base + (tid >> 1);
    int half = tid & 1;
    float v = wsh[n];
    int rank = 0;
    int q0 = half * (NN / 2), q1 = q0 + NN / 2;
    for (int q = q0; q < q1; q++) {
        float u = wsh[q];
        rank += (u > v) || (u == v && q < n);
    }
    rank += __shfl_xor_sync(0xffffffffu, rank, 1);
    if (half == 0 && rank < KEY) g_topi[b * KEY + rank] = n;
}

// ================= K9: gather keypoints + knn outputs =================
__global__ __launch_bounds__(256) void k_outputs(const float* __restrict__ src,
                                                 const int* __restrict__ src_idx,
                                                 float* __restrict__ out) {
    int g = blockIdx.x * blockDim.x + threadIdx.x;
    if (g >= BB * KEY * KC) return;
    int kk = g % KC;
    int j = (g / KC) % KEY;
    int b = g / (KC * KEY);
    int tn = g_topi[b * KEY + j];
    const float* sp = src + (size_t)b * 3 * NN;
    const float* cb = g_corr + (size_t)b * 3 * NN;
    int id = src_idx[((size_t)b * NN + tn) * KC + kk];
    const float* R = g_R + b * 9;
    const float* tt = g_t + b * 3;
    float s0 = sp[tn], s1 = sp[NN + tn], s2 = sp[2 * NN + tn];
    float q0 = sp[id], q1 = sp[NN + id], q2 = sp[2 * NN + id];
    float st[3], sq[3];
    #pragma unroll
    for (int c = 0; c < 3; c++) {
        st[c] = R[c * 3] * s0 + R[c * 3 + 1] * s1 + R[c * 3 + 2] * s2 + tt[c];
        sq[c] = R[c * 3] * q0 + R[c * 3 + 1] * q1 + R[c * 3 + 2] * q2 + tt[c];
    }
    float* skk = out + OFF_SKNN;
    float* tkk = out + OFF_TKNN;
    #pragma unroll
    for (int c = 0; c < 3; c++) {
        size_t o = (((size_t)b * 3 + c) * KEY + j) * KC + kk;
        skk[o] = st[c] - sq[c];
        tkk[o] = cb[c * NN + tn] - cb[c * NN + id];
    }
    if (kk == 0) {
        float* skp = out + OFF_SKP;
        float* tkp = out + OFF_TKP;
        #pragma unroll
        for (int c = 0; c < 3; c++) {
            skp[((size_t)b * 3 + c) * KEY + j] = sp[c * NN + tn];
            tkp[((size_t)b * 3 + c) * KEY + j] = cb[c * NN + tn];
        }
    }
}

// ================= K10: loss =================
__global__ __launch_bounds__(256) void k_loss(float* __restrict__ out) {
    __shared__ double red[256];
    int tid = threadIdx.x;
    double s = 0.0;
    for (int p = tid; p < BB * KEY; p += 256) {
        int b = p / KEY;
        int tn = g_topi[p];
        double pm = (double)g_rowmax[b * NN + tn];
        s += -log(pm + 1e-15);
    }
    red[tid] = s; __syncthreads();
    for (int st = 128; st > 0; st >>= 1) { if (tid < st) red[tid] += red[tid + st]; __syncthreads(); }
    if (tid == 0) out[OFF_LOSS] = (float)(red[0] / (double)(BB * KEY));
}

// ================= launch =================
extern "C" void kernel_launch(void* const* d_in, const int* in_sizes, int n_in,
                              void* d_out, int out_size) {
    const float* src      = (const float*)d_in[0];
    const float* tgt      = (const float*)d_in[1];
    const float* se       = (const float*)d_in[2];
    const float* te       = (const float*)d_in[3];
    const float* src_knn  = (const float*)d_in[4];
    const float* W1 = (const float*)d_in[6];
    const float* b1 = (const float*)d_in[7];
    const float* W2 = (const float*)d_in[8];
    const float* b2 = (const float*)d_in[9];
    const float* W3 = (const float*)d_in[10];
    const float* b3 = (const float*)d_in[11];
    const int* src_idx  = (const int*)d_in[12];
    const int* src_idx1 = (const int*)d_in[13];
    const int* idx2     = (const int*)d_in[14];
    float* out = (float*)d_out;

    const int smem_gemm = 2 * STAGE_E * (int)sizeof(__nv_bfloat16);  // 92160 B
    cudaFuncSetAttribute(k_gemm, cudaFuncAttributeMaxDynamicSharedMemorySize, smem_gemm);

    dim3 gp(CC / 32, NN / 32, 2 * BB);
    k_prep<<<gp, 256>>>(se, te);
    k_norms<<<(BB * NN + BB * MM) / 256, 256>>>(se, te);
    dim3 gg(MM / 64, NN / 128, BB);
    k_gemm<<<gg, 256, smem_gemm>>>();
    k_invsum<<<(BB * NN * 32 + 255) / 256, 256>>>();
    dim3 gr(NN / NT, BB);
    k_rowpipe<<<gr, 256>>>(tgt, src_idx1, idx2);
    k_disc<<<BB * NN / 8, 128>>>(src, src_knn, src_idx, W1, b1, W2, b2, W3, b3);
    k_wsoftmax<<<BB, 256>>>();
    k_rigid<<<BB, 256>>>(src, out);
    k_topk<<<BB * 16, 256>>>();
    k_outputs<<<(BB * KEY * KC + 255) / 256, 256>>>(src, src_idx, out);
    k_loss<<<1, 256>>>(out);
}